// round 11
// baseline (speedup 1.0000x reference)
#include <cuda_runtime.h>
#include <cuda_bf16.h>
#include <stdint.h>

#define NB   4
#define SS   4096
#define DD   1024
#define AA   1024
#define NTOK (NB * SS)
#define K3P  (3 * DD)
#define K3S  (3 * SS)

// Scratch (device globals: allocation-free rule)
__device__ float g_V[(size_t)NTOK * AA];
__device__ float g_P[(size_t)NB * SS * SS];
__device__ __nv_bfloat16 g_xA[(size_t)NTOK * K3P];
__device__ __nv_bfloat16 g_QA[(size_t)NTOK * K3P];
__device__ __nv_bfloat16 g_KB[(size_t)NTOK * K3P];
__device__ __nv_bfloat16 g_CA[(size_t)NTOK * K3P];
__device__ __nv_bfloat16 g_PA[(size_t)NTOK * (size_t)K3S];
__device__ __nv_bfloat16 g_VT[(size_t)NB * AA * (size_t)K3S];
__device__ __nv_bfloat16 g_WqB[(size_t)AA * K3P];
__device__ __nv_bfloat16 g_WkB[(size_t)AA * K3P];
__device__ __nv_bfloat16 g_WvB[(size_t)AA * K3P];
__device__ __nv_bfloat16 g_WoB[(size_t)DD * K3P];

// ---------------- PTX helpers (sm_103 baseline: no tcgen05/TMA) ----------
__device__ __forceinline__ uint32_t smem_u32(const void* p) {
    uint32_t a;
    asm("{ .reg .u64 t; cvta.to.shared.u64 t, %1; cvt.u32.u64 %0, t; }" : "=r"(a) : "l"(p));
    return a;
}
__device__ __forceinline__ void cp16(uint32_t dst, const void* src) {
    asm volatile("cp.async.cg.shared.global [%0], [%1], 16;" :: "r"(dst), "l"(src));
}
#define CP_COMMIT() asm volatile("cp.async.commit_group;" ::: "memory")
#define CP_WAIT2()  asm volatile("cp.async.wait_group 2;" ::: "memory")

#define LDSM4(R0, R1, R2, R3, ADDR) \
    asm volatile("ldmatrix.sync.aligned.m8n8.x4.shared.b16 {%0,%1,%2,%3}, [%4];" \
                 : "=r"(R0), "=r"(R1), "=r"(R2), "=r"(R3) : "r"(ADDR))

__device__ __forceinline__ void mma16816(float* d, const uint32_t* a, const uint32_t* b) {
    asm volatile(
        "mma.sync.aligned.m16n8k16.row.col.f32.bf16.bf16.f32 "
        "{%0,%1,%2,%3}, {%4,%5,%6,%7}, {%8,%9}, {%0,%1,%2,%3};"
        : "+f"(d[0]), "+f"(d[1]), "+f"(d[2]), "+f"(d[3])
        : "r"(a[0]), "r"(a[1]), "r"(a[2]), "r"(a[3]), "r"(b[0]), "r"(b[1]));
}

// ---------------------------------------------------------------------------
// GEMM: out[M,N] = alpha * A''[M,K3](bf16) * B''[N,K3](bf16)^T + bias
// BM=256, BN=128, BK=32. 8 warps (4x2), warp tile 64x64. 4-stage cp.async.
// 256 threads, 1 CTA/SM. One __syncthreads per BK iteration.
// MODE 0: fp32 out[M,N]
// MODE 1: bf16 split-A out[M,3N] = [hi | lo | hi]
// MODE 2: bf16 split-B out[M,3N] = [hi | hi | lo]
// ---------------------------------------------------------------------------
#define BK 32
#define NSTAGE 4
#define A_PART 16384                    // 256 rows x 64B
#define STG_BYTES 24576                 // A 16KB + B 8KB
#define GEMM_SMEM (NSTAGE * STG_BYTES)  // 98304

template <int MODE>
__global__ void __launch_bounds__(256, 1) mma_gemm_kernel(
    const __nv_bfloat16* __restrict__ A, const __nv_bfloat16* __restrict__ B,
    const float* __restrict__ bias, void* __restrict__ outv,
    int N, int K3, float alpha, int rowsA, int rowsB)
{
    extern __shared__ __align__(128) char smem[];
    const uint32_t sb = smem_u32(smem);
    const int tid  = threadIdx.x;
    const int lane = tid & 31;
    const int wid  = tid >> 5;
    const int wm   = wid >> 1;       // 0..3
    const int wn   = wid & 1;        // 0..1

    const int aRow = blockIdx.z * rowsA + blockIdx.y * 256;
    const int bRow = blockIdx.z * rowsB + blockIdx.x * 128;

    // cp.async loader: 256 threads; 4 A-rows + 2 B-rows of one 16B chunk each
    const int lc      = tid & 3;                 // 16B chunk within 64B row
    const int baseRow = tid >> 2;                // 0..63
    const int swL     = (baseRow >> 1) & 3;      // row step 64 keeps phase
    const uint32_t chunk = (uint32_t)((lc ^ swL) * 16);
    uint32_t dA[4], dB[2];
    const __nv_bfloat16 *gA[4], *gB[2];
    #pragma unroll
    for (int r = 0; r < 4; ++r) {
        const int row = baseRow + r * 64;        // 0..255
        dA[r] = (uint32_t)(row * 64) + chunk;
        gA[r] = A + (long)(aRow + row) * K3 + lc * 8;
    }
    #pragma unroll
    for (int r = 0; r < 2; ++r) {
        const int row = baseRow + r * 64;        // 0..127
        dB[r] = (uint32_t)(row * 64) + chunk;
        gB[r] = B + (long)(bRow + row) * K3 + lc * 8;
    }

    // ldmatrix lane addressing
    const int rA  = wm * 64 + (lane & 15);
    const int khA = lane >> 4;
    const int swA = (rA >> 1) & 3;
    const int rB  = wn * 64 + (lane & 7) + ((lane >> 4) << 3);
    const int khB = (lane >> 3) & 1;
    const int swB = (rB >> 1) & 3;

    float acc[4][8][4];
    #pragma unroll
    for (int i = 0; i < 4; ++i)
        #pragma unroll
        for (int j = 0; j < 8; ++j)
            #pragma unroll
            for (int e = 0; e < 4; ++e) acc[i][j][e] = 0.0f;

    const int NT = K3 / BK;

    // prologue: stages 0..2
    #pragma unroll
    for (int s = 0; s < NSTAGE - 1; ++s) {
        const uint32_t ab = sb + s * STG_BYTES;
        const long go = (long)s * BK;
        #pragma unroll
        for (int r = 0; r < 4; ++r) cp16(ab + dA[r], gA[r] + go);
        #pragma unroll
        for (int r = 0; r < 2; ++r) cp16(ab + A_PART + dB[r], gB[r] + go);
        CP_COMMIT();
    }

    for (int kt = 0; kt < NT; ++kt) {
        CP_WAIT2();            // stage kt resident
        __syncthreads();       // all warps done reading buffer (kt-1)%4

        if (kt + NSTAGE - 1 < NT) {
            const int s = (kt + NSTAGE - 1) % NSTAGE;
            const uint32_t ab = sb + s * STG_BYTES;
            const long go = (long)(kt + NSTAGE - 1) * BK;
            #pragma unroll
            for (int r = 0; r < 4; ++r) cp16(ab + dA[r], gA[r] + go);
            #pragma unroll
            for (int r = 0; r < 2; ++r) cp16(ab + A_PART + dB[r], gB[r] + go);
        }
        CP_COMMIT();

        const uint32_t ab = sb + (kt % NSTAGE) * STG_BYTES;
        const uint32_t bb = ab + A_PART;

        #pragma unroll
        for (int ks = 0; ks < 2; ++ks) {
            uint32_t a[4][4], b[8][2];
            #pragma unroll
            for (int mf = 0; mf < 4; ++mf) {
                const uint32_t ad = ab + (uint32_t)((rA + mf * 16) * 64 +
                                     (((ks * 2 + khA) ^ swA) * 16));
                LDSM4(a[mf][0], a[mf][1], a[mf][2], a[mf][3], ad);
            }
            #pragma unroll
            for (int nfp = 0; nfp < 4; ++nfp) {
                const uint32_t bd = bb + (uint32_t)((rB + nfp * 16) * 64 +
                                     (((ks * 2 + khB) ^ swB) * 16));
                LDSM4(b[nfp * 2][0], b[nfp * 2][1], b[nfp * 2 + 1][0], b[nfp * 2 + 1][1], bd);
            }
            #pragma unroll
            for (int mf = 0; mf < 4; ++mf)
                #pragma unroll
                for (int nf = 0; nf < 8; ++nf)
                    mma16816(acc[mf][nf], a[mf], b[nf]);
        }
    }

    // Epilogue
    const long rBase   = (long)(blockIdx.z * rowsA + blockIdx.y * 256) + wm * 64;
    const int  colBase = blockIdx.x * 128 + wn * 64;

    if (MODE == 0) {
        float* out = (float*)outv;
        #pragma unroll
        for (int mf = 0; mf < 4; ++mf) {
            const long r0 = rBase + mf * 16 + (lane >> 2);
            #pragma unroll
            for (int nf = 0; nf < 8; ++nf) {
                const int cc = colBase + nf * 8 + (lane & 3) * 2;
                float2 bv = make_float2(0.0f, 0.0f);
                if (bias) bv = *(const float2*)(bias + cc);
                float2 v0 = make_float2(acc[mf][nf][0] * alpha + bv.x,
                                        acc[mf][nf][1] * alpha + bv.y);
                float2 v1 = make_float2(acc[mf][nf][2] * alpha + bv.x,
                                        acc[mf][nf][3] * alpha + bv.y);
                *(float2*)(out + r0 * N + cc)       = v0;
                *(float2*)(out + (r0 + 8) * N + cc) = v1;
            }
        }
    } else {
        __nv_bfloat16* ob = (__nv_bfloat16*)outv;
        const long ldo = 3L * N;
        #pragma unroll
        for (int mf = 0; mf < 4; ++mf) {
            const long r0 = rBase + mf * 16 + (lane >> 2);
            #pragma unroll
            for (int nf = 0; nf < 8; ++nf) {
                const int cc = colBase + nf * 8 + (lane & 3) * 2;
                float2 bv = make_float2(0.0f, 0.0f);
                if (bias) bv = *(const float2*)(bias + cc);
                #pragma unroll
                for (int h = 0; h < 2; ++h) {
                    const long rr = r0 + h * 8;
                    float vx = acc[mf][nf][h * 2 + 0] * alpha + bv.x;
                    float vy = acc[mf][nf][h * 2 + 1] * alpha + bv.y;
                    union { __nv_bfloat16 b[2]; uint32_t u; } H, L;
                    H.b[0] = __float2bfloat16(vx);
                    H.b[1] = __float2bfloat16(vy);
                    L.b[0] = __float2bfloat16(vx - __bfloat162float(H.b[0]));
                    L.b[1] = __float2bfloat16(vy - __bfloat162float(H.b[1]));
                    *(uint32_t*)(ob + rr * ldo + cc)          = H.u;
                    *(uint32_t*)(ob + rr * ldo + N + cc)      = (MODE == 1) ? L.u : H.u;
                    *(uint32_t*)(ob + rr * ldo + 2L * N + cc) = (MODE == 1) ? H.u : L.u;
                }
            }
        }
    }
}

// ---------------- fp32 -> split-3 bf16 converters -------------------------
template <int PAT>
__global__ __launch_bounds__(256) void conv_kernel(
    const float* __restrict__ in, __nv_bfloat16* __restrict__ out, int C, long total4)
{
    const long t = blockIdx.x * 256L + threadIdx.x;
    if (t >= total4) return;
    const long i = t * 4;
    const long r = i / C;
    const int  c = (int)(i - r * C);
    float4 v = *(const float4*)(in + i);
    float vv[4] = {v.x, v.y, v.z, v.w};
    union { __nv_bfloat16 b[4]; uint2 u; } H, L;
    #pragma unroll
    for (int j = 0; j < 4; ++j) {
        H.b[j] = __float2bfloat16(vv[j]);
        L.b[j] = __float2bfloat16(vv[j] - __bfloat162float(H.b[j]));
    }
    const long base = r * (3L * C) + c;
    *(uint2*)(out + base) = H.u;
    if (PAT == 0) {
        *(uint2*)(out + base + C)      = L.u;
        *(uint2*)(out + base + 2L * C) = H.u;
    } else {
        *(uint2*)(out + base + C)      = H.u;
        *(uint2*)(out + base + 2L * C) = L.u;
    }
}

// V [NB,S,A] fp32 -> Vt'' [NB, A, 3S] bf16 (B pattern)
__global__ void __launch_bounds__(1024) convT_kernel(
    const float* __restrict__ V, __nv_bfloat16* __restrict__ Vt)
{
    __shared__ float t[32][33];
    const int b  = blockIdx.z;
    const int s0 = blockIdx.y * 32, a0 = blockIdx.x * 32;
    const int x = threadIdx.x, y = threadIdx.y;
    t[y][x] = V[((long)b * SS + s0 + y) * AA + a0 + x];
    __syncthreads();
    const float v = t[x][y];
    const __nv_bfloat16 hi = __float2bfloat16(v);
    const __nv_bfloat16 lo = __float2bfloat16(v - __bfloat162float(hi));
    const long base = ((long)b * AA + a0 + y) * (long)K3S + (s0 + x);
    Vt[base]           = hi;
    Vt[base + SS]      = hi;
    Vt[base + 2L * SS] = lo;
}

// ---------------- fused softmax + split-A (hi|lo|hi) ----------------------
__global__ __launch_bounds__(256) void softmax_split_kernel(
    const float* __restrict__ P, __nv_bfloat16* __restrict__ PA)
{
    const float* p = P + (long)blockIdx.x * SS;
    __nv_bfloat16* o = PA + (long)blockIdx.x * (3L * SS);
    const int tid = threadIdx.x, lane = tid & 31, wrp = tid >> 5;
    __shared__ float red[8];

    float v[16];
    #pragma unroll
    for (int j = 0; j < 4; ++j) {
        float4 t = *(const float4*)(p + j * 1024 + tid * 4);
        v[j * 4 + 0] = t.x; v[j * 4 + 1] = t.y; v[j * 4 + 2] = t.z; v[j * 4 + 3] = t.w;
    }

    float mx = v[0];
    #pragma unroll
    for (int i = 1; i < 16; ++i) mx = fmaxf(mx, v[i]);
    #pragma unroll
    for (int off = 16; off; off >>= 1) mx = fmaxf(mx, __shfl_xor_sync(~0u, mx, off));
    if (lane == 0) red[wrp] = mx;
    __syncthreads();
    mx = red[0];
    #pragma unroll
    for (int w = 1; w < 8; ++w) mx = fmaxf(mx, red[w]);
    __syncthreads();

    float sum = 0.0f;
    #pragma unroll
    for (int i = 0; i < 16; ++i) { v[i] = __expf(v[i] - mx); sum += v[i]; }
    #pragma unroll
    for (int off = 16; off; off >>= 1) sum += __shfl_xor_sync(~0u, sum, off);
    if (lane == 0) red[wrp] = sum;
    __syncthreads();
    sum = 0.0f;
    #pragma unroll
    for (int w = 0; w < 8; ++w) sum += red[w];
    const float inv = 1.0f / sum;

    #pragma unroll
    for (int j = 0; j < 4; ++j) {
        const int col = j * 1024 + tid * 4;
        #pragma unroll
        for (int q = 0; q < 2; ++q) {
            float ax = v[j * 4 + q * 2 + 0] * inv;
            float ay = v[j * 4 + q * 2 + 1] * inv;
            union { __nv_bfloat16 b[2]; uint32_t u; } H, L;
            H.b[0] = __float2bfloat16(ax);
            H.b[1] = __float2bfloat16(ay);
            L.b[0] = __float2bfloat16(ax - __bfloat162float(H.b[0]));
            L.b[1] = __float2bfloat16(ay - __bfloat162float(H.b[1]));
            *(uint32_t*)(o + col + q * 2)            = H.u;
            *(uint32_t*)(o + SS + col + q * 2)       = L.u;
            *(uint32_t*)(o + 2L * SS + col + q * 2)  = H.u;
        }
    }
}

// ---------------- host ----------------
extern "C" void kernel_launch(void* const* d_in, const int* in_sizes, int n_in,
                              void* d_out, int out_size)
{
    const float* x  = (const float*)d_in[0];
    const float* Wq = (const float*)d_in[1];
    const float* bq = (const float*)d_in[2];
    const float* Wk = (const float*)d_in[3];
    const float* bk = (const float*)d_in[4];
    const float* Wv = (const float*)d_in[5];
    const float* bv = (const float*)d_in[6];
    const float* Wo = (const float*)d_in[7];
    const float* bo = (const float*)d_in[8];
    float* out = (float*)d_out;

    float *V, *P;
    __nv_bfloat16 *xA, *QA, *KB, *CA, *PA, *VT, *WqB, *WkB, *WvB, *WoB;
    cudaGetSymbolAddress((void**)&V, g_V);
    cudaGetSymbolAddress((void**)&P, g_P);
    cudaGetSymbolAddress((void**)&xA, g_xA);
    cudaGetSymbolAddress((void**)&QA, g_QA);
    cudaGetSymbolAddress((void**)&KB, g_KB);
    cudaGetSymbolAddress((void**)&CA, g_CA);
    cudaGetSymbolAddress((void**)&PA, g_PA);
    cudaGetSymbolAddress((void**)&VT, g_VT);
    cudaGetSymbolAddress((void**)&WqB, g_WqB);
    cudaGetSymbolAddress((void**)&WkB, g_WkB);
    cudaGetSymbolAddress((void**)&WvB, g_WvB);
    cudaGetSymbolAddress((void**)&WoB, g_WoB);

    cudaFuncSetAttribute(mma_gemm_kernel<0>,
                         cudaFuncAttributeMaxDynamicSharedMemorySize, GEMM_SMEM);
    cudaFuncSetAttribute(mma_gemm_kernel<1>,
                         cudaFuncAttributeMaxDynamicSharedMemorySize, GEMM_SMEM);
    cudaFuncSetAttribute(mma_gemm_kernel<2>,
                         cudaFuncAttributeMaxDynamicSharedMemorySize, GEMM_SMEM);

    const float scale = 0.03125f;  // 1/sqrt(1024)

    // split inputs (x + weights only — Q/K/ctx splits are fused in GEMM epilogues)
    long t4 = (long)NTOK * DD / 4;
    conv_kernel<0><<<(unsigned)((t4 + 255) / 256), 256>>>(x, xA, DD, t4);
    long w4 = (long)AA * DD / 4;
    conv_kernel<1><<<(unsigned)((w4 + 255) / 256), 256>>>(Wq, WqB, DD, w4);
    conv_kernel<1><<<(unsigned)((w4 + 255) / 256), 256>>>(Wk, WkB, DD, w4);
    conv_kernel<1><<<(unsigned)((w4 + 255) / 256), 256>>>(Wv, WvB, DD, w4);
    conv_kernel<1><<<(unsigned)((w4 + 255) / 256), 256>>>(Wo, WoB, AA, w4);

    // projections: Q -> split-A, K -> split-B, V -> fp32 (needs transpose)
    dim3 gproj(AA / 128, NTOK / 256, 1);
    mma_gemm_kernel<1><<<gproj, 256, GEMM_SMEM>>>(xA, WqB, bq, QA, AA, K3P, 1.0f, NTOK, AA);
    mma_gemm_kernel<2><<<gproj, 256, GEMM_SMEM>>>(xA, WkB, bk, KB, AA, K3P, 1.0f, NTOK, AA);
    mma_gemm_kernel<0><<<gproj, 256, GEMM_SMEM>>>(xA, WvB, bv, V,  AA, K3P, 1.0f, NTOK, AA);

    convT_kernel<<<dim3(AA / 32, SS / 32, NB), dim3(32, 32)>>>(V, VT);

    // scores: per-batch [4096,3072] x [4096,3072]^T * scale -> fp32 P
    dim3 gsc(SS / 128, SS / 256, NB);
    mma_gemm_kernel<0><<<gsc, 256, GEMM_SMEM>>>(QA, KB, nullptr, P, SS, K3P, scale, SS, SS);

    // fused softmax + split-A -> PA
    softmax_split_kernel<<<NB * SS, 256>>>(P, PA);

    // ctx: per-batch [4096,12288] x [1024,12288]^T -> split-A CA
    dim3 gctx(AA / 128, SS / 256, NB);
    mma_gemm_kernel<1><<<gctx, 256, GEMM_SMEM>>>(PA, VT, nullptr, CA, AA, K3S, 1.0f, SS, AA);

    // output projection -> fp32 out
    mma_gemm_kernel<0><<<gproj, 256, GEMM_SMEM>>>(CA, WoB, bo, out, DD, K3P, 1.0f, NTOK, DD);
}

// round 12
// speedup vs baseline: 1.1940x; 1.1940x over previous
#include <cuda_runtime.h>
#include <cuda_bf16.h>
#include <stdint.h>

#define NB   4
#define SS   4096
#define DD   1024
#define AA   1024
#define NTOK (NB * SS)

// Physical split buffers store [hi | lo] (2 sections); the GEMM remaps the
// logical 3-section pattern (A=[hi|lo|hi], B=[hi|hi|lo]) onto them.
__device__ float g_V[(size_t)NTOK * AA];
__device__ float g_P[(size_t)NB * SS * SS];
__device__ __nv_bfloat16 g_xA[(size_t)NTOK * 2 * DD];
__device__ __nv_bfloat16 g_QA[(size_t)NTOK * 2 * AA];
__device__ __nv_bfloat16 g_KB[(size_t)NTOK * 2 * AA];
__device__ __nv_bfloat16 g_CA[(size_t)NTOK * 2 * AA];
__device__ __nv_bfloat16 g_PA[(size_t)NTOK * 2 * SS];
__device__ __nv_bfloat16 g_VT[(size_t)NB * AA * 2 * SS];
__device__ __nv_bfloat16 g_WqB[(size_t)AA * 2 * DD];
__device__ __nv_bfloat16 g_WkB[(size_t)AA * 2 * DD];
__device__ __nv_bfloat16 g_WvB[(size_t)AA * 2 * DD];
__device__ __nv_bfloat16 g_WoB[(size_t)DD * 2 * AA];

// ---------------- PTX helpers (sm_103 baseline: no tcgen05/TMA) ----------
__device__ __forceinline__ uint32_t smem_u32(const void* p) {
    uint32_t a;
    asm("{ .reg .u64 t; cvta.to.shared.u64 t, %1; cvt.u32.u64 %0, t; }" : "=r"(a) : "l"(p));
    return a;
}
__device__ __forceinline__ void cp16(uint32_t dst, const void* src) {
    asm volatile("cp.async.cg.shared.global [%0], [%1], 16;" :: "r"(dst), "l"(src));
}
#define CP_COMMIT() asm volatile("cp.async.commit_group;" ::: "memory")
#define CP_WAIT2()  asm volatile("cp.async.wait_group 2;" ::: "memory")

#define LDSM4(R0, R1, R2, R3, ADDR) \
    asm volatile("ldmatrix.sync.aligned.m8n8.x4.shared.b16 {%0,%1,%2,%3}, [%4];" \
                 : "=r"(R0), "=r"(R1), "=r"(R2), "=r"(R3) : "r"(ADDR))

__device__ __forceinline__ void mma16816(float* d, const uint32_t* a, const uint32_t* b) {
    asm volatile(
        "mma.sync.aligned.m16n8k16.row.col.f32.bf16.bf16.f32 "
        "{%0,%1,%2,%3}, {%4,%5,%6,%7}, {%8,%9}, {%0,%1,%2,%3};"
        : "+f"(d[0]), "+f"(d[1]), "+f"(d[2]), "+f"(d[3])
        : "r"(a[0]), "r"(a[1]), "r"(a[2]), "r"(a[3]), "r"(b[0]), "r"(b[1]));
}

// ---------------------------------------------------------------------------
// GEMM: out[M,N] = alpha * A''[M,3K] * B''[N,3K]^T + bias   (logical split-3)
// Physical A,B are [rows, 2K] = [hi|lo]. Loader remaps:
//   A section 2 -> section 0 (hi), B section 1 -> section 0 (hi).
// BM=BN=128, BK=32, 8 warps (2x4, warp tile 64x32), 4-stage cp.async,
// 256 threads, 2 CTAs/SM (R9 config — proven HMMA-saturating).
// MODE 0: fp32 out[M,N];  MODE 1: bf16 [hi|lo] out[M,2N]
// ---------------------------------------------------------------------------
#define BK 32
#define NSTAGE 4
#define STG_BYTES 16384                 // A 8KB + B 8KB
#define GEMM_SMEM (NSTAGE * STG_BYTES)  // 65536

template <int MODE>
__global__ void __launch_bounds__(256, 2) mma_gemm_kernel(
    const __nv_bfloat16* __restrict__ A, const __nv_bfloat16* __restrict__ B,
    const float* __restrict__ bias, void* __restrict__ outv,
    int N, int Ksec, float alpha, int rowsA, int rowsB)
{
    extern __shared__ __align__(128) char smem[];
    const uint32_t sb = smem_u32(smem);
    const int tid  = threadIdx.x;
    const int lane = tid & 31;
    const int wid  = tid >> 5;
    const int wm   = wid >> 2;       // 0..1
    const int wn   = wid & 3;        // 0..3

    const long ld = 2L * Ksec;       // physical row stride (elements)
    const int aRow = blockIdx.z * rowsA + blockIdx.y * 128;
    const int bRow = blockIdx.z * rowsB + blockIdx.x * 128;

    // cp.async loader: 2 A-chunks + 2 B-chunks of 16B per thread
    const int lr0 = tid >> 2;            // 0..63
    const int lr1 = lr0 + 64;
    const int lc  = tid & 3;
    const int sw0 = (lr0 >> 1) & 3;
    const uint32_t dA0 = (uint32_t)(lr0 * 64 + ((lc ^ sw0) * 16));
    const uint32_t dA1 = (uint32_t)(lr1 * 64 + ((lc ^ sw0) * 16));
    const __nv_bfloat16* gA0 = A + (long)(aRow + lr0) * ld + lc * 8;
    const __nv_bfloat16* gA1 = A + (long)(aRow + lr1) * ld + lc * 8;
    const __nv_bfloat16* gB0 = B + (long)(bRow + lr0) * ld + lc * 8;
    const __nv_bfloat16* gB1 = B + (long)(bRow + lr1) * ld + lc * 8;

    // ldmatrix lane addressing
    const int rA  = wm * 64 + (lane & 15);
    const int khA = lane >> 4;
    const int swA = (rA >> 1) & 3;
    const int rB  = wn * 32 + (lane & 7) + ((lane >> 4) << 3);
    const int khB = (lane >> 3) & 1;
    const int swB = (rB >> 1) & 3;

    float acc[4][4][4];
    #pragma unroll
    for (int i = 0; i < 4; ++i)
        #pragma unroll
        for (int j = 0; j < 4; ++j)
            #pragma unroll
            for (int e = 0; e < 4; ++e) acc[i][j][e] = 0.0f;

    const int NT = (3 * Ksec) / BK;
    const long K1 = Ksec, K2 = 2L * Ksec;

    // prologue: stages 0..2 (gO < Ksec always: Ksec >= 1024)
    #pragma unroll
    for (int s = 0; s < NSTAGE - 1; ++s) {
        const uint32_t ab = sb + s * STG_BYTES;
        const long go = (long)s * BK;
        cp16(ab + dA0,        gA0 + go);
        cp16(ab + dA1,        gA1 + go);
        cp16(ab + 8192 + dA0, gB0 + go);
        cp16(ab + 8192 + dA1, gB1 + go);
        CP_COMMIT();
    }

    for (int kt = 0; kt < NT; ++kt) {
        CP_WAIT2();            // stage kt resident
        __syncthreads();       // all warps done reading buffer (kt-1)%4

        if (kt + NSTAGE - 1 < NT) {
            const int s = (kt + NSTAGE - 1) % NSTAGE;
            const uint32_t ab = sb + s * STG_BYTES;
            const long gO = (long)(kt + NSTAGE - 1) * BK;
            const long aO = (gO < K2) ? gO : gO - K2;   // A: [hi|lo|hi] -> [hi|lo]
            const long bO = (gO < K1) ? gO : gO - K1;   // B: [hi|hi|lo] -> [hi|lo]
            cp16(ab + dA0,        gA0 + aO);
            cp16(ab + dA1,        gA1 + aO);
            cp16(ab + 8192 + dA0, gB0 + bO);
            cp16(ab + 8192 + dA1, gB1 + bO);
        }
        CP_COMMIT();

        const uint32_t ab = sb + (kt % NSTAGE) * STG_BYTES;
        const uint32_t bb = ab + 8192;

        #pragma unroll
        for (int ks = 0; ks < 2; ++ks) {
            uint32_t a[4][4], b[4][2];
            #pragma unroll
            for (int mf = 0; mf < 4; ++mf) {
                const uint32_t ad = ab + (uint32_t)((rA + mf * 16) * 64 +
                                     (((ks * 2 + khA) ^ swA) * 16));
                LDSM4(a[mf][0], a[mf][1], a[mf][2], a[mf][3], ad);
            }
            #pragma unroll
            for (int nfp = 0; nfp < 2; ++nfp) {
                const uint32_t bd = bb + (uint32_t)((rB + nfp * 16) * 64 +
                                     (((ks * 2 + khB) ^ swB) * 16));
                LDSM4(b[nfp * 2][0], b[nfp * 2][1], b[nfp * 2 + 1][0], b[nfp * 2 + 1][1], bd);
            }
            #pragma unroll
            for (int mf = 0; mf < 4; ++mf)
                #pragma unroll
                for (int nf = 0; nf < 4; ++nf)
                    mma16816(acc[mf][nf], a[mf], b[nf]);
        }
    }

    // Epilogue
    const long rBase   = (long)(blockIdx.z * rowsA + blockIdx.y * 128) + wm * 64;
    const int  colBase = blockIdx.x * 128 + wn * 32;

    if (MODE == 0) {
        float* out = (float*)outv;
        #pragma unroll
        for (int mf = 0; mf < 4; ++mf) {
            const long r0 = rBase + mf * 16 + (lane >> 2);
            #pragma unroll
            for (int nf = 0; nf < 4; ++nf) {
                const int cc = colBase + nf * 8 + (lane & 3) * 2;
                float2 bv = make_float2(0.0f, 0.0f);
                if (bias) bv = *(const float2*)(bias + cc);
                float2 v0 = make_float2(acc[mf][nf][0] * alpha + bv.x,
                                        acc[mf][nf][1] * alpha + bv.y);
                float2 v1 = make_float2(acc[mf][nf][2] * alpha + bv.x,
                                        acc[mf][nf][3] * alpha + bv.y);
                *(float2*)(out + r0 * N + cc)       = v0;
                *(float2*)(out + (r0 + 8) * N + cc) = v1;
            }
        }
    } else {
        __nv_bfloat16* ob = (__nv_bfloat16*)outv;
        const long ldo = 2L * N;
        #pragma unroll
        for (int mf = 0; mf < 4; ++mf) {
            const long r0 = rBase + mf * 16 + (lane >> 2);
            #pragma unroll
            for (int nf = 0; nf < 4; ++nf) {
                const int cc = colBase + nf * 8 + (lane & 3) * 2;
                float2 bv = make_float2(0.0f, 0.0f);
                if (bias) bv = *(const float2*)(bias + cc);
                #pragma unroll
                for (int h = 0; h < 2; ++h) {
                    const long rr = r0 + h * 8;
                    float vx = acc[mf][nf][h * 2 + 0] * alpha + bv.x;
                    float vy = acc[mf][nf][h * 2 + 1] * alpha + bv.y;
                    union { __nv_bfloat16 b[2]; uint32_t u; } H, L;
                    H.b[0] = __float2bfloat16(vx);
                    H.b[1] = __float2bfloat16(vy);
                    L.b[0] = __float2bfloat16(vx - __bfloat162float(H.b[0]));
                    L.b[1] = __float2bfloat16(vy - __bfloat162float(H.b[1]));
                    *(uint32_t*)(ob + rr * ldo + cc)     = H.u;
                    *(uint32_t*)(ob + rr * ldo + N + cc) = L.u;
                }
            }
        }
    }
}

// ---------------- fp32 -> [hi|lo] bf16 converter ---------------------------
__global__ __launch_bounds__(256) void conv_kernel(
    const float* __restrict__ in, __nv_bfloat16* __restrict__ out, int C, long total4)
{
    const long t = blockIdx.x * 256L + threadIdx.x;
    if (t >= total4) return;
    const long i = t * 4;
    const long r = i / C;
    const int  c = (int)(i - r * C);
    float4 v = *(const float4*)(in + i);
    float vv[4] = {v.x, v.y, v.z, v.w};
    union { __nv_bfloat16 b[4]; uint2 u; } H, L;
    #pragma unroll
    for (int j = 0; j < 4; ++j) {
        H.b[j] = __float2bfloat16(vv[j]);
        L.b[j] = __float2bfloat16(vv[j] - __bfloat162float(H.b[j]));
    }
    const long base = r * (2L * C) + c;
    *(uint2*)(out + base)     = H.u;
    *(uint2*)(out + base + C) = L.u;
}

// V [NB,S,A] fp32 -> Vt [NB, A, 2S] bf16 [hi|lo]
__global__ void __launch_bounds__(1024) convT_kernel(
    const float* __restrict__ V, __nv_bfloat16* __restrict__ Vt)
{
    __shared__ float t[32][33];
    const int b  = blockIdx.z;
    const int s0 = blockIdx.y * 32, a0 = blockIdx.x * 32;
    const int x = threadIdx.x, y = threadIdx.y;
    t[y][x] = V[((long)b * SS + s0 + y) * AA + a0 + x];
    __syncthreads();
    const float v = t[x][y];
    const __nv_bfloat16 hi = __float2bfloat16(v);
    const __nv_bfloat16 lo = __float2bfloat16(v - __bfloat162float(hi));
    const long base = ((long)b * AA + a0 + y) * (2L * SS) + (s0 + x);
    Vt[base]      = hi;
    Vt[base + SS] = lo;
}

// ---------------- fused softmax + [hi|lo] split ----------------------------
__global__ __launch_bounds__(256) void softmax_split_kernel(
    const float* __restrict__ P, __nv_bfloat16* __restrict__ PA)
{
    const float* p = P + (long)blockIdx.x * SS;
    __nv_bfloat16* o = PA + (long)blockIdx.x * (2L * SS);
    const int tid = threadIdx.x, lane = tid & 31, wrp = tid >> 5;
    __shared__ float red[8];

    float v[16];
    #pragma unroll
    for (int j = 0; j < 4; ++j) {
        float4 t = *(const float4*)(p + j * 1024 + tid * 4);
        v[j * 4 + 0] = t.x; v[j * 4 + 1] = t.y; v[j * 4 + 2] = t.z; v[j * 4 + 3] = t.w;
    }

    float mx = v[0];
    #pragma unroll
    for (int i = 1; i < 16; ++i) mx = fmaxf(mx, v[i]);
    #pragma unroll
    for (int off = 16; off; off >>= 1) mx = fmaxf(mx, __shfl_xor_sync(~0u, mx, off));
    if (lane == 0) red[wrp] = mx;
    __syncthreads();
    mx = red[0];
    #pragma unroll
    for (int w = 1; w < 8; ++w) mx = fmaxf(mx, red[w]);
    __syncthreads();

    float sum = 0.0f;
    #pragma unroll
    for (int i = 0; i < 16; ++i) { v[i] = __expf(v[i] - mx); sum += v[i]; }
    #pragma unroll
    for (int off = 16; off; off >>= 1) sum += __shfl_xor_sync(~0u, sum, off);
    if (lane == 0) red[wrp] = sum;
    __syncthreads();
    sum = 0.0f;
    #pragma unroll
    for (int w = 0; w < 8; ++w) sum += red[w];
    const float inv = 1.0f / sum;

    #pragma unroll
    for (int j = 0; j < 4; ++j) {
        const int col = j * 1024 + tid * 4;
        #pragma unroll
        for (int q = 0; q < 2; ++q) {
            float ax = v[j * 4 + q * 2 + 0] * inv;
            float ay = v[j * 4 + q * 2 + 1] * inv;
            union { __nv_bfloat16 b[2]; uint32_t u; } H, L;
            H.b[0] = __float2bfloat16(ax);
            H.b[1] = __float2bfloat16(ay);
            L.b[0] = __float2bfloat16(ax - __bfloat162float(H.b[0]));
            L.b[1] = __float2bfloat16(ay - __bfloat162float(H.b[1]));
            *(uint32_t*)(o + col + q * 2)      = H.u;
            *(uint32_t*)(o + SS + col + q * 2) = L.u;
        }
    }
}

// ---------------- host ----------------
extern "C" void kernel_launch(void* const* d_in, const int* in_sizes, int n_in,
                              void* d_out, int out_size)
{
    const float* x  = (const float*)d_in[0];
    const float* Wq = (const float*)d_in[1];
    const float* bq = (const float*)d_in[2];
    const float* Wk = (const float*)d_in[3];
    const float* bk = (const float*)d_in[4];
    const float* Wv = (const float*)d_in[5];
    const float* bv = (const float*)d_in[6];
    const float* Wo = (const float*)d_in[7];
    const float* bo = (const float*)d_in[8];
    float* out = (float*)d_out;

    float *V, *P;
    __nv_bfloat16 *xA, *QA, *KB, *CA, *PA, *VT, *WqB, *WkB, *WvB, *WoB;
    cudaGetSymbolAddress((void**)&V, g_V);
    cudaGetSymbolAddress((void**)&P, g_P);
    cudaGetSymbolAddress((void**)&xA, g_xA);
    cudaGetSymbolAddress((void**)&QA, g_QA);
    cudaGetSymbolAddress((void**)&KB, g_KB);
    cudaGetSymbolAddress((void**)&CA, g_CA);
    cudaGetSymbolAddress((void**)&PA, g_PA);
    cudaGetSymbolAddress((void**)&VT, g_VT);
    cudaGetSymbolAddress((void**)&WqB, g_WqB);
    cudaGetSymbolAddress((void**)&WkB, g_WkB);
    cudaGetSymbolAddress((void**)&WvB, g_WvB);
    cudaGetSymbolAddress((void**)&WoB, g_WoB);

    cudaFuncSetAttribute(mma_gemm_kernel<0>,
                         cudaFuncAttributeMaxDynamicSharedMemorySize, GEMM_SMEM);
    cudaFuncSetAttribute(mma_gemm_kernel<1>,
                         cudaFuncAttributeMaxDynamicSharedMemorySize, GEMM_SMEM);

    const float scale = 0.03125f;  // 1/sqrt(1024)

    // split inputs to [hi|lo]
    long t4 = (long)NTOK * DD / 4;
    conv_kernel<<<(unsigned)((t4 + 255) / 256), 256>>>(x, xA, DD, t4);
    long w4 = (long)AA * DD / 4;
    conv_kernel<<<(unsigned)((w4 + 255) / 256), 256>>>(Wq, WqB, DD, w4);
    conv_kernel<<<(unsigned)((w4 + 255) / 256), 256>>>(Wk, WkB, DD, w4);
    conv_kernel<<<(unsigned)((w4 + 255) / 256), 256>>>(Wv, WvB, DD, w4);
    conv_kernel<<<(unsigned)((w4 + 255) / 256), 256>>>(Wo, WoB, AA, w4);

    // projections: Q,K -> [hi|lo] split out; V -> fp32 (for transpose)
    dim3 gproj(AA / 128, NTOK / 128, 1);
    mma_gemm_kernel<1><<<gproj, 256, GEMM_SMEM>>>(xA, WqB, bq, QA, AA, DD, 1.0f, NTOK, AA);
    mma_gemm_kernel<1><<<gproj, 256, GEMM_SMEM>>>(xA, WkB, bk, KB, AA, DD, 1.0f, NTOK, AA);
    mma_gemm_kernel<0><<<gproj, 256, GEMM_SMEM>>>(xA, WvB, bv, V,  AA, DD, 1.0f, NTOK, AA);

    convT_kernel<<<dim3(AA / 32, SS / 32, NB), dim3(32, 32)>>>(V, VT);

    // scores: per-batch [4096 x 3*1024] x [4096 x 3*1024]^T * scale -> fp32 P
    dim3 gsc(SS / 128, SS / 128, NB);
    mma_gemm_kernel<0><<<gsc, 256, GEMM_SMEM>>>(QA, KB, nullptr, P, SS, AA, scale, SS, SS);

    // fused softmax + [hi|lo] split -> PA
    softmax_split_kernel<<<NB * SS, 256>>>(P, PA);

    // ctx: per-batch [4096 x 3*4096] x [1024 x 3*4096]^T -> [hi|lo] CA
    dim3 gctx(AA / 128, SS / 128, NB);
    mma_gemm_kernel<1><<<gctx, 256, GEMM_SMEM>>>(PA, VT, nullptr, CA, AA, SS, 1.0f, SS, AA);

    // output projection -> fp32 out
    mma_gemm_kernel<0><<<gproj, 256, GEMM_SMEM>>>(CA, WoB, bo, out, DD, AA, 1.0f, NTOK, DD);
}

// round 13
// speedup vs baseline: 1.4996x; 1.2559x over previous
#include <cuda_runtime.h>
#include <cuda_bf16.h>
#include <cuda_fp16.h>
#include <stdint.h>

#define NB   4
#define SS   4096
#define DD   1024
#define AA   1024
#define NTOK (NB * SS)

// Scratch (device globals: allocation-free rule)
__device__ float g_V[(size_t)NTOK * AA];
__device__ float g_P[(size_t)NB * SS * SS];
__device__ __nv_bfloat16 g_xA[(size_t)NTOK * 2 * DD];   // bf16 [hi|lo]
__device__ __half        g_QA[(size_t)NTOK * 2 * AA];   // fp16 [hi|lo]
__device__ __half        g_KB[(size_t)NTOK * AA];       // fp16 [hi]
__device__ __nv_bfloat16 g_CA[(size_t)NTOK * 2 * AA];   // bf16 [hi|lo]
__device__ __half        g_PA[(size_t)NTOK * 2 * SS];   // fp16 [hi|lo]
__device__ __half        g_VT[(size_t)NB * AA * SS];    // fp16 [hi], transposed
__device__ __nv_bfloat16 g_WqB[(size_t)AA * 2 * DD];
__device__ __nv_bfloat16 g_WkB[(size_t)AA * 2 * DD];
__device__ __nv_bfloat16 g_WvB[(size_t)AA * 2 * DD];
__device__ __nv_bfloat16 g_WoB[(size_t)DD * 2 * AA];

// ---------------- PTX helpers (sm_103 baseline: no tcgen05/TMA) ----------
__device__ __forceinline__ uint32_t smem_u32(const void* p) {
    uint32_t a;
    asm("{ .reg .u64 t; cvta.to.shared.u64 t, %1; cvt.u32.u64 %0, t; }" : "=r"(a) : "l"(p));
    return a;
}
__device__ __forceinline__ void cp16(uint32_t dst, const void* src) {
    asm volatile("cp.async.cg.shared.global [%0], [%1], 16;" :: "r"(dst), "l"(src));
}
#define CP_COMMIT() asm volatile("cp.async.commit_group;" ::: "memory")
#define CP_WAIT2()  asm volatile("cp.async.wait_group 2;" ::: "memory")

#define LDSM4(R0, R1, R2, R3, ADDR) \
    asm volatile("ldmatrix.sync.aligned.m8n8.x4.shared.b16 {%0,%1,%2,%3}, [%4];" \
                 : "=r"(R0), "=r"(R1), "=r"(R2), "=r"(R3) : "r"(ADDR))

__device__ __forceinline__ void mma_bf16(float* d, const uint32_t* a, const uint32_t* b) {
    asm volatile(
        "mma.sync.aligned.m16n8k16.row.col.f32.bf16.bf16.f32 "
        "{%0,%1,%2,%3}, {%4,%5,%6,%7}, {%8,%9}, {%0,%1,%2,%3};"
        : "+f"(d[0]), "+f"(d[1]), "+f"(d[2]), "+f"(d[3])
        : "r"(a[0]), "r"(a[1]), "r"(a[2]), "r"(a[3]), "r"(b[0]), "r"(b[1]));
}
__device__ __forceinline__ void mma_f16(float* d, const uint32_t* a, const uint32_t* b) {
    asm volatile(
        "mma.sync.aligned.m16n8k16.row.col.f32.f16.f16.f32 "
        "{%0,%1,%2,%3}, {%4,%5,%6,%7}, {%8,%9}, {%0,%1,%2,%3};"
        : "+f"(d[0]), "+f"(d[1]), "+f"(d[2]), "+f"(d[3])
        : "r"(a[0]), "r"(a[1]), "r"(a[2]), "r"(a[3]), "r"(b[0]), "r"(b[1]));
}

// ---------------------------------------------------------------------------
// GEMM: out[M,N] = alpha * A''[M,SPLIT*K] * B''[N,SPLIT*K]^T + bias
// SPLIT=3 (bf16): A logical [hi|lo|hi] on physical [hi|lo] (ldA=2K);
//                 B logical [hi|hi|lo] on physical [hi|lo] (ldB=2K).
// SPLIT=2 (fp16): A = [hi|lo] physical (ldA=2K); B logical [hi|hi] on
//                 physical [hi] (ldB=K)  =>  out = A_exact * fp16(B).
// Remaps (both splits): aO = gO<2K ? gO : gO-2K ;  bO = gO<K ? gO : gO-K.
// BM=BN=128, BK=32, 8 warps (2x4, warp 64x32), 4-stage cp.async, 2 CTA/SM.
// MODE 0: fp32 [M,N] | 1: bf16 [hi|lo] [M,2N] | 3: fp16 [hi|lo] [M,2N] | 4: fp16 hi [M,N]
// ---------------------------------------------------------------------------
#define BK 32
#define NSTAGE 4
#define STG_BYTES 16384
#define GEMM_SMEM (NSTAGE * STG_BYTES)

template <int MODE, int SPLIT, bool F16>
__global__ void __launch_bounds__(256, 2) mma_gemm_kernel(
    const void* __restrict__ Av, const void* __restrict__ Bv,
    const float* __restrict__ bias, void* __restrict__ outv,
    int N, int Ksec, float alpha, int rowsA, int rowsB)
{
    extern __shared__ __align__(128) char smem[];
    const uint32_t sb = smem_u32(smem);
    const uint16_t* A = (const uint16_t*)Av;
    const uint16_t* B = (const uint16_t*)Bv;
    const int tid  = threadIdx.x;
    const int lane = tid & 31;
    const int wid  = tid >> 5;
    const int wm   = wid >> 2;       // 0..1
    const int wn   = wid & 3;        // 0..3

    const long ldA = 2L * Ksec;
    const long ldB = (SPLIT == 3) ? 2L * Ksec : (long)Ksec;
    const int aRow = blockIdx.z * rowsA + blockIdx.y * 128;
    const int bRow = blockIdx.z * rowsB + blockIdx.x * 128;

    // cp.async loader: 2 A-chunks + 2 B-chunks of 16B per thread
    const int lr0 = tid >> 2;            // 0..63
    const int lr1 = lr0 + 64;
    const int lc  = tid & 3;
    const int sw0 = (lr0 >> 1) & 3;
    const uint32_t dA0 = (uint32_t)(lr0 * 64 + ((lc ^ sw0) * 16));
    const uint32_t dA1 = (uint32_t)(lr1 * 64 + ((lc ^ sw0) * 16));
    const uint16_t* gA0 = A + (long)(aRow + lr0) * ldA + lc * 8;
    const uint16_t* gA1 = A + (long)(aRow + lr1) * ldA + lc * 8;
    const uint16_t* gB0 = B + (long)(bRow + lr0) * ldB + lc * 8;
    const uint16_t* gB1 = B + (long)(bRow + lr1) * ldB + lc * 8;

    // ldmatrix lane addressing
    const int rA  = wm * 64 + (lane & 15);
    const int khA = lane >> 4;
    const int swA = (rA >> 1) & 3;
    const int rB  = wn * 32 + (lane & 7) + ((lane >> 4) << 3);
    const int khB = (lane >> 3) & 1;
    const int swB = (rB >> 1) & 3;

    float acc[4][4][4];
    #pragma unroll
    for (int i = 0; i < 4; ++i)
        #pragma unroll
        for (int j = 0; j < 4; ++j)
            #pragma unroll
            for (int e = 0; e < 4; ++e) acc[i][j][e] = 0.0f;

    const int NT = (SPLIT * Ksec) / BK;
    const long K1 = Ksec, K2 = 2L * Ksec;

    // prologue: stages 0..2 (gO < Ksec always since Ksec >= 1024)
    #pragma unroll
    for (int s = 0; s < NSTAGE - 1; ++s) {
        const uint32_t ab = sb + s * STG_BYTES;
        const long go = (long)s * BK;
        cp16(ab + dA0,        gA0 + go);
        cp16(ab + dA1,        gA1 + go);
        cp16(ab + 8192 + dA0, gB0 + go);
        cp16(ab + 8192 + dA1, gB1 + go);
        CP_COMMIT();
    }

    for (int kt = 0; kt < NT; ++kt) {
        CP_WAIT2();
        __syncthreads();

        if (kt + NSTAGE - 1 < NT) {
            const int s = (kt + NSTAGE - 1) % NSTAGE;
            const uint32_t ab = sb + s * STG_BYTES;
            const long gO = (long)(kt + NSTAGE - 1) * BK;
            const long aO = (gO < K2) ? gO : gO - K2;
            const long bO = (gO < K1) ? gO : gO - K1;
            cp16(ab + dA0,        gA0 + aO);
            cp16(ab + dA1,        gA1 + aO);
            cp16(ab + 8192 + dA0, gB0 + bO);
            cp16(ab + 8192 + dA1, gB1 + bO);
        }
        CP_COMMIT();

        const uint32_t ab = sb + (kt % NSTAGE) * STG_BYTES;
        const uint32_t bb = ab + 8192;

        #pragma unroll
        for (int ks = 0; ks < 2; ++ks) {
            uint32_t a[4][4], b[4][2];
            #pragma unroll
            for (int mf = 0; mf < 4; ++mf) {
                const uint32_t ad = ab + (uint32_t)((rA + mf * 16) * 64 +
                                     (((ks * 2 + khA) ^ swA) * 16));
                LDSM4(a[mf][0], a[mf][1], a[mf][2], a[mf][3], ad);
            }
            #pragma unroll
            for (int nfp = 0; nfp < 2; ++nfp) {
                const uint32_t bd = bb + (uint32_t)((rB + nfp * 16) * 64 +
                                     (((ks * 2 + khB) ^ swB) * 16));
                LDSM4(b[nfp * 2][0], b[nfp * 2][1], b[nfp * 2 + 1][0], b[nfp * 2 + 1][1], bd);
            }
            #pragma unroll
            for (int mf = 0; mf < 4; ++mf)
                #pragma unroll
                for (int nf = 0; nf < 4; ++nf) {
                    if (F16) mma_f16(acc[mf][nf], a[mf], b[nf]);
                    else     mma_bf16(acc[mf][nf], a[mf], b[nf]);
                }
        }
    }

    // Epilogue
    const long rBase   = (long)(blockIdx.z * rowsA + blockIdx.y * 128) + wm * 64;
    const int  colBase = blockIdx.x * 128 + wn * 32;

    #pragma unroll
    for (int mf = 0; mf < 4; ++mf) {
        const long r0 = rBase + mf * 16 + (lane >> 2);
        #pragma unroll
        for (int nf = 0; nf < 4; ++nf) {
            const int cc = colBase + nf * 8 + (lane & 3) * 2;
            float2 bv = make_float2(0.0f, 0.0f);
            if (bias) bv = *(const float2*)(bias + cc);
            float vx0 = acc[mf][nf][0] * alpha + bv.x;
            float vy0 = acc[mf][nf][1] * alpha + bv.y;
            float vx1 = acc[mf][nf][2] * alpha + bv.x;
            float vy1 = acc[mf][nf][3] * alpha + bv.y;

            if (MODE == 0) {
                float* out = (float*)outv;
                *(float2*)(out + r0 * N + cc)       = make_float2(vx0, vy0);
                *(float2*)(out + (r0 + 8) * N + cc) = make_float2(vx1, vy1);
            } else if (MODE == 1) {
                __nv_bfloat16* ob = (__nv_bfloat16*)outv;
                const long ldo = 2L * N;
                float vs[2][2] = {{vx0, vy0}, {vx1, vy1}};
                #pragma unroll
                for (int h = 0; h < 2; ++h) {
                    const long rr = r0 + h * 8;
                    union { __nv_bfloat16 b[2]; uint32_t u; } H, L;
                    H.b[0] = __float2bfloat16(vs[h][0]);
                    H.b[1] = __float2bfloat16(vs[h][1]);
                    L.b[0] = __float2bfloat16(vs[h][0] - __bfloat162float(H.b[0]));
                    L.b[1] = __float2bfloat16(vs[h][1] - __bfloat162float(H.b[1]));
                    *(uint32_t*)(ob + rr * ldo + cc)     = H.u;
                    *(uint32_t*)(ob + rr * ldo + N + cc) = L.u;
                }
            } else if (MODE == 3) {
                __half* ob = (__half*)outv;
                const long ldo = 2L * N;
                float vs[2][2] = {{vx0, vy0}, {vx1, vy1}};
                #pragma unroll
                for (int h = 0; h < 2; ++h) {
                    const long rr = r0 + h * 8;
                    union { __half b[2]; uint32_t u; } H, L;
                    H.b[0] = __float2half_rn(vs[h][0]);
                    H.b[1] = __float2half_rn(vs[h][1]);
                    L.b[0] = __float2half_rn(vs[h][0] - __half2float(H.b[0]));
                    L.b[1] = __float2half_rn(vs[h][1] - __half2float(H.b[1]));
                    *(uint32_t*)(ob + rr * ldo + cc)     = H.u;
                    *(uint32_t*)(ob + rr * ldo + N + cc) = L.u;
                }
            } else {  // MODE 4: fp16 hi only
                __half* ob = (__half*)outv;
                float vs[2][2] = {{vx0, vy0}, {vx1, vy1}};
                #pragma unroll
                for (int h = 0; h < 2; ++h) {
                    const long rr = r0 + h * 8;
                    union { __half b[2]; uint32_t u; } H;
                    H.b[0] = __float2half_rn(vs[h][0]);
                    H.b[1] = __float2half_rn(vs[h][1]);
                    *(uint32_t*)(ob + rr * N + cc) = H.u;
                }
            }
        }
    }
}

// ---------------- fp32 -> [hi|lo] bf16 converter ---------------------------
__global__ __launch_bounds__(256) void conv_kernel(
    const float* __restrict__ in, __nv_bfloat16* __restrict__ out, int C, long total4)
{
    const long t = blockIdx.x * 256L + threadIdx.x;
    if (t >= total4) return;
    const long i = t * 4;
    const long r = i / C;
    const int  c = (int)(i - r * C);
    float4 v = *(const float4*)(in + i);
    float vv[4] = {v.x, v.y, v.z, v.w};
    union { __nv_bfloat16 b[4]; uint2 u; } H, L;
    #pragma unroll
    for (int j = 0; j < 4; ++j) {
        H.b[j] = __float2bfloat16(vv[j]);
        L.b[j] = __float2bfloat16(vv[j] - __bfloat162float(H.b[j]));
    }
    const long base = r * (2L * C) + c;
    *(uint2*)(out + base)     = H.u;
    *(uint2*)(out + base + C) = L.u;
}

// V [NB,S,A] fp32 -> Vt [NB, A, S] fp16 (hi only)
__global__ void __launch_bounds__(1024) convT_kernel(
    const float* __restrict__ V, __half* __restrict__ Vt)
{
    __shared__ float t[32][33];
    const int b  = blockIdx.z;
    const int s0 = blockIdx.y * 32, a0 = blockIdx.x * 32;
    const int x = threadIdx.x, y = threadIdx.y;
    t[y][x] = V[((long)b * SS + s0 + y) * AA + a0 + x];
    __syncthreads();
    Vt[((long)b * AA + a0 + y) * (long)SS + (s0 + x)] = __float2half_rn(t[x][y]);
}

// ---------------- fused softmax + fp16 [hi|lo] split -----------------------
__global__ __launch_bounds__(256) void softmax_split_kernel(
    const float* __restrict__ P, __half* __restrict__ PA)
{
    const float* p = P + (long)blockIdx.x * SS;
    __half* o = PA + (long)blockIdx.x * (2L * SS);
    const int tid = threadIdx.x, lane = tid & 31, wrp = tid >> 5;
    __shared__ float red[8];

    float v[16];
    #pragma unroll
    for (int j = 0; j < 4; ++j) {
        float4 t = *(const float4*)(p + j * 1024 + tid * 4);
        v[j * 4 + 0] = t.x; v[j * 4 + 1] = t.y; v[j * 4 + 2] = t.z; v[j * 4 + 3] = t.w;
    }

    float mx = v[0];
    #pragma unroll
    for (int i = 1; i < 16; ++i) mx = fmaxf(mx, v[i]);
    #pragma unroll
    for (int off = 16; off; off >>= 1) mx = fmaxf(mx, __shfl_xor_sync(~0u, mx, off));
    if (lane == 0) red[wrp] = mx;
    __syncthreads();
    mx = red[0];
    #pragma unroll
    for (int w = 1; w < 8; ++w) mx = fmaxf(mx, red[w]);
    __syncthreads();

    float sum = 0.0f;
    #pragma unroll
    for (int i = 0; i < 16; ++i) { v[i] = __expf(v[i] - mx); sum += v[i]; }
    #pragma unroll
    for (int off = 16; off; off >>= 1) sum += __shfl_xor_sync(~0u, sum, off);
    if (lane == 0) red[wrp] = sum;
    __syncthreads();
    sum = 0.0f;
    #pragma unroll
    for (int w = 0; w < 8; ++w) sum += red[w];
    const float inv = 1.0f / sum;

    #pragma unroll
    for (int j = 0; j < 4; ++j) {
        const int col = j * 1024 + tid * 4;
        #pragma unroll
        for (int q = 0; q < 2; ++q) {
            float ax = v[j * 4 + q * 2 + 0] * inv;
            float ay = v[j * 4 + q * 2 + 1] * inv;
            union { __half b[2]; uint32_t u; } H, L;
            H.b[0] = __float2half_rn(ax);
            H.b[1] = __float2half_rn(ay);
            L.b[0] = __float2half_rn(ax - __half2float(H.b[0]));
            L.b[1] = __float2half_rn(ay - __half2float(H.b[1]));
            *(uint32_t*)(o + col + q * 2)      = H.u;
            *(uint32_t*)(o + SS + col + q * 2) = L.u;
        }
    }
}

// ---------------- host ----------------
extern "C" void kernel_launch(void* const* d_in, const int* in_sizes, int n_in,
                              void* d_out, int out_size)
{
    const float* x  = (const float*)d_in[0];
    const float* Wq = (const float*)d_in[1];
    const float* bq = (const float*)d_in[2];
    const float* Wk = (const float*)d_in[3];
    const float* bk = (const float*)d_in[4];
    const float* Wv = (const float*)d_in[5];
    const float* bv = (const float*)d_in[6];
    const float* Wo = (const float*)d_in[7];
    const float* bo = (const float*)d_in[8];
    float* out = (float*)d_out;

    float *V, *P;
    __nv_bfloat16 *xA, *CA, *WqB, *WkB, *WvB, *WoB;
    __half *QA, *KB, *PA, *VT;
    cudaGetSymbolAddress((void**)&V, g_V);
    cudaGetSymbolAddress((void**)&P, g_P);
    cudaGetSymbolAddress((void**)&xA, g_xA);
    cudaGetSymbolAddress((void**)&QA, g_QA);
    cudaGetSymbolAddress((void**)&KB, g_KB);
    cudaGetSymbolAddress((void**)&CA, g_CA);
    cudaGetSymbolAddress((void**)&PA, g_PA);
    cudaGetSymbolAddress((void**)&VT, g_VT);
    cudaGetSymbolAddress((void**)&WqB, g_WqB);
    cudaGetSymbolAddress((void**)&WkB, g_WkB);
    cudaGetSymbolAddress((void**)&WvB, g_WvB);
    cudaGetSymbolAddress((void**)&WoB, g_WoB);

    cudaFuncSetAttribute((const void*)mma_gemm_kernel<0, 3, false>,
                         cudaFuncAttributeMaxDynamicSharedMemorySize, GEMM_SMEM);
    cudaFuncSetAttribute((const void*)mma_gemm_kernel<1, 2, true>,
                         cudaFuncAttributeMaxDynamicSharedMemorySize, GEMM_SMEM);
    cudaFuncSetAttribute((const void*)mma_gemm_kernel<3, 3, false>,
                         cudaFuncAttributeMaxDynamicSharedMemorySize, GEMM_SMEM);
    cudaFuncSetAttribute((const void*)mma_gemm_kernel<4, 3, false>,
                         cudaFuncAttributeMaxDynamicSharedMemorySize, GEMM_SMEM);
    cudaFuncSetAttribute((const void*)mma_gemm_kernel<0, 2, true>,
                         cudaFuncAttributeMaxDynamicSharedMemorySize, GEMM_SMEM);

    const float scale = 0.03125f;  // 1/sqrt(1024)

    // split inputs to bf16 [hi|lo]
    long t4 = (long)NTOK * DD / 4;
    conv_kernel<<<(unsigned)((t4 + 255) / 256), 256>>>(x, xA, DD, t4);
    long w4 = (long)AA * DD / 4;
    conv_kernel<<<(unsigned)((w4 + 255) / 256), 256>>>(Wq, WqB, DD, w4);
    conv_kernel<<<(unsigned)((w4 + 255) / 256), 256>>>(Wk, WkB, DD, w4);
    conv_kernel<<<(unsigned)((w4 + 255) / 256), 256>>>(Wv, WvB, DD, w4);
    conv_kernel<<<(unsigned)((w4 + 255) / 256), 256>>>(Wo, WoB, AA, w4);

    // projections (bf16 split-3): Q -> fp16 [hi|lo], K -> fp16 hi, V -> fp32
    dim3 gproj(AA / 128, NTOK / 128, 1);
    mma_gemm_kernel<3, 3, false><<<gproj, 256, GEMM_SMEM>>>(xA, WqB, bq, QA, AA, DD, 1.0f, NTOK, AA);
    mma_gemm_kernel<4, 3, false><<<gproj, 256, GEMM_SMEM>>>(xA, WkB, bk, KB, AA, DD, 1.0f, NTOK, AA);
    mma_gemm_kernel<0, 3, false><<<gproj, 256, GEMM_SMEM>>>(xA, WvB, bv, V,  AA, DD, 1.0f, NTOK, AA);

    convT_kernel<<<dim3(AA / 32, SS / 32, NB), dim3(32, 32)>>>(V, VT);

    // scores (fp16 split-2): per-batch q_exact . fp16(k) * scale -> fp32 P
    dim3 gsc(SS / 128, SS / 128, NB);
    mma_gemm_kernel<0, 2, true><<<gsc, 256, GEMM_SMEM>>>(QA, KB, nullptr, P, SS, AA, scale, SS, SS);

    // fused softmax + fp16 [hi|lo] split -> PA
    softmax_split_kernel<<<NB * SS, 256>>>(P, PA);

    // ctx (fp16 split-2): per-batch p_exact . fp16(v) -> bf16 [hi|lo] CA
    dim3 gctx(AA / 128, SS / 128, NB);
    mma_gemm_kernel<1, 2, true><<<gctx, 256, GEMM_SMEM>>>(PA, VT, nullptr, CA, AA, SS, 1.0f, SS, AA);

    // output projection (bf16 split-3) -> fp32 out
    mma_gemm_kernel<0, 3, false><<<gproj, 256, GEMM_SMEM>>>(CA, WoB, bo, out, DD, AA, 1.0f, NTOK, DD);
}

// round 14
// speedup vs baseline: 2.0486x; 1.3662x over previous
#include <cuda_runtime.h>
#include <cuda_fp16.h>
#include <stdint.h>

#define NB   4
#define SS   4096
#define DD   1024
#define AA   1024
#define NTOK (NB * SS)

// Scratch (device globals: allocation-free rule)
__device__ float  g_P [(size_t)NB * SS * SS];          // fp32 scores
__device__ __half g_xA[(size_t)NTOK * 2 * DD];         // x  fp16 [hi|lo]
__device__ __half g_QA[(size_t)NTOK * 2 * AA];         // Q  fp16 [hi|lo]
__device__ __half g_KB[(size_t)NTOK * AA];             // K  fp16 hi
__device__ __half g_Vh[(size_t)NTOK * AA];             // V  fp16 hi
__device__ __half g_VT[(size_t)NB * AA * SS];          // V^T fp16 hi
__device__ __half g_PH[(size_t)NTOK * SS];             // attn fp16 hi
__device__ __half g_CA[(size_t)NTOK * 2 * AA];         // ctx fp16 [hi|lo]
__device__ __half g_WqH[(size_t)AA * DD];
__device__ __half g_WkH[(size_t)AA * DD];
__device__ __half g_WvH[(size_t)AA * DD];
__device__ __half g_WoH[(size_t)DD * AA];

// ---------------- PTX helpers (sm_103 baseline: no tcgen05/TMA) ----------
__device__ __forceinline__ uint32_t smem_u32(const void* p) {
    uint32_t a;
    asm("{ .reg .u64 t; cvta.to.shared.u64 t, %1; cvt.u32.u64 %0, t; }" : "=r"(a) : "l"(p));
    return a;
}
__device__ __forceinline__ void cp16(uint32_t dst, const void* src) {
    asm volatile("cp.async.cg.shared.global [%0], [%1], 16;" :: "r"(dst), "l"(src));
}
#define CP_COMMIT() asm volatile("cp.async.commit_group;" ::: "memory")
#define CP_WAIT2()  asm volatile("cp.async.wait_group 2;" ::: "memory")

#define LDSM4(R0, R1, R2, R3, ADDR) \
    asm volatile("ldmatrix.sync.aligned.m8n8.x4.shared.b16 {%0,%1,%2,%3}, [%4];" \
                 : "=r"(R0), "=r"(R1), "=r"(R2), "=r"(R3) : "r"(ADDR))

__device__ __forceinline__ void mma_f16(float* d, const uint32_t* a, const uint32_t* b) {
    asm volatile(
        "mma.sync.aligned.m16n8k16.row.col.f32.f16.f16.f32 "
        "{%0,%1,%2,%3}, {%4,%5,%6,%7}, {%8,%9}, {%0,%1,%2,%3};"
        : "+f"(d[0]), "+f"(d[1]), "+f"(d[2]), "+f"(d[3])
        : "r"(a[0]), "r"(a[1]), "r"(a[2]), "r"(a[3]), "r"(b[0]), "r"(b[1]));
}

// ---------------------------------------------------------------------------
// GEMM (all fp16, fp32 accum): out[M,N] = alpha*A'[M,SPLIT*K]*B'[N,SPLIT*K]^T + bias
// SPLIT=2: A physical [hi|lo] (ldA=2K, no remap); B logical [hi|hi] on
//          physical [hi] (ldB=K, bO = gO<K ? gO : gO-K).  out = A_exact*fp16(B).
// SPLIT=1: A,B both [hi] single pass (ldA=ldB=K).         out = fp16(A)*fp16(B).
// BM=BN=128, BK=32, 8 warps (2x4, warp 64x32), 4-stage cp.async, 2 CTA/SM.
// MODE 0: fp32 [M,N]+bias | 3: fp16 [hi|lo] [M,2N]+bias | 4: fp16 hi [M,N]+bias
// ---------------------------------------------------------------------------
#define BK 32
#define NSTAGE 4
#define STG_BYTES 16384
#define GEMM_SMEM (NSTAGE * STG_BYTES)

template <int MODE, int SPLIT>
__global__ void __launch_bounds__(256, 2) mma_gemm_kernel(
    const __half* __restrict__ A, const __half* __restrict__ B,
    const float* __restrict__ bias, void* __restrict__ outv,
    int N, int Ksec, float alpha, int rowsA, int rowsB)
{
    extern __shared__ __align__(128) char smem[];
    const uint32_t sb = smem_u32(smem);
    const int tid  = threadIdx.x;
    const int lane = tid & 31;
    const int wid  = tid >> 5;
    const int wm   = wid >> 2;       // 0..1
    const int wn   = wid & 3;        // 0..3

    const long ldA = (long)SPLIT * Ksec;
    const long ldB = (long)Ksec;
    const int aRow = blockIdx.z * rowsA + blockIdx.y * 128;
    const int bRow = blockIdx.z * rowsB + blockIdx.x * 128;

    // cp.async loader: 2 A-chunks + 2 B-chunks of 16B per thread
    const int lr0 = tid >> 2;            // 0..63
    const int lr1 = lr0 + 64;
    const int lc  = tid & 3;
    const int sw0 = (lr0 >> 1) & 3;
    const uint32_t dA0 = (uint32_t)(lr0 * 64 + ((lc ^ sw0) * 16));
    const uint32_t dA1 = (uint32_t)(lr1 * 64 + ((lc ^ sw0) * 16));
    const __half* gA0 = A + (long)(aRow + lr0) * ldA + lc * 8;
    const __half* gA1 = A + (long)(aRow + lr1) * ldA + lc * 8;
    const __half* gB0 = B + (long)(bRow + lr0) * ldB + lc * 8;
    const __half* gB1 = B + (long)(bRow + lr1) * ldB + lc * 8;

    // ldmatrix lane addressing
    const int rA  = wm * 64 + (lane & 15);
    const int khA = lane >> 4;
    const int swA = (rA >> 1) & 3;
    const int rB  = wn * 32 + (lane & 7) + ((lane >> 4) << 3);
    const int khB = (lane >> 3) & 1;
    const int swB = (rB >> 1) & 3;

    float acc[4][4][4];
    #pragma unroll
    for (int i = 0; i < 4; ++i)
        #pragma unroll
        for (int j = 0; j < 4; ++j)
            #pragma unroll
            for (int e = 0; e < 4; ++e) acc[i][j][e] = 0.0f;

    const int NT = (SPLIT * Ksec) / BK;
    const long K1 = Ksec;

    // prologue: stages 0..2 (gO < Ksec always since Ksec >= 1024)
    #pragma unroll
    for (int s = 0; s < NSTAGE - 1; ++s) {
        const uint32_t ab = sb + s * STG_BYTES;
        const long go = (long)s * BK;
        cp16(ab + dA0,        gA0 + go);
        cp16(ab + dA1,        gA1 + go);
        cp16(ab + 8192 + dA0, gB0 + go);
        cp16(ab + 8192 + dA1, gB1 + go);
        CP_COMMIT();
    }

    for (int kt = 0; kt < NT; ++kt) {
        CP_WAIT2();
        __syncthreads();

        if (kt + NSTAGE - 1 < NT) {
            const int s = (kt + NSTAGE - 1) % NSTAGE;
            const uint32_t ab = sb + s * STG_BYTES;
            const long gO = (long)(kt + NSTAGE - 1) * BK;
            const long bO = (SPLIT == 2) ? ((gO < K1) ? gO : gO - K1) : gO;
            cp16(ab + dA0,        gA0 + gO);
            cp16(ab + dA1,        gA1 + gO);
            cp16(ab + 8192 + dA0, gB0 + bO);
            cp16(ab + 8192 + dA1, gB1 + bO);
        }
        CP_COMMIT();

        const uint32_t ab = sb + (kt % NSTAGE) * STG_BYTES;
        const uint32_t bb = ab + 8192;

        #pragma unroll
        for (int ks = 0; ks < 2; ++ks) {
            uint32_t a[4][4], b[4][2];
            #pragma unroll
            for (int mf = 0; mf < 4; ++mf) {
                const uint32_t ad = ab + (uint32_t)((rA + mf * 16) * 64 +
                                     (((ks * 2 + khA) ^ swA) * 16));
                LDSM4(a[mf][0], a[mf][1], a[mf][2], a[mf][3], ad);
            }
            #pragma unroll
            for (int nfp = 0; nfp < 2; ++nfp) {
                const uint32_t bd = bb + (uint32_t)((rB + nfp * 16) * 64 +
                                     (((ks * 2 + khB) ^ swB) * 16));
                LDSM4(b[nfp * 2][0], b[nfp * 2][1], b[nfp * 2 + 1][0], b[nfp * 2 + 1][1], bd);
            }
            #pragma unroll
            for (int mf = 0; mf < 4; ++mf)
                #pragma unroll
                for (int nf = 0; nf < 4; ++nf)
                    mma_f16(acc[mf][nf], a[mf], b[nf]);
        }
    }

    // Epilogue
    const long rBase   = (long)(blockIdx.z * rowsA + blockIdx.y * 128) + wm * 64;
    const int  colBase = blockIdx.x * 128 + wn * 32;

    #pragma unroll
    for (int mf = 0; mf < 4; ++mf) {
        const long r0 = rBase + mf * 16 + (lane >> 2);
        #pragma unroll
        for (int nf = 0; nf < 4; ++nf) {
            const int cc = colBase + nf * 8 + (lane & 3) * 2;
            float2 bv = make_float2(0.0f, 0.0f);
            if (bias) bv = *(const float2*)(bias + cc);
            float vs[2][2] = {
                {acc[mf][nf][0] * alpha + bv.x, acc[mf][nf][1] * alpha + bv.y},
                {acc[mf][nf][2] * alpha + bv.x, acc[mf][nf][3] * alpha + bv.y}};

            if (MODE == 0) {
                float* out = (float*)outv;
                *(float2*)(out + r0 * N + cc)       = make_float2(vs[0][0], vs[0][1]);
                *(float2*)(out + (r0 + 8) * N + cc) = make_float2(vs[1][0], vs[1][1]);
            } else if (MODE == 3) {
                __half* ob = (__half*)outv;
                const long ldo = 2L * N;
                #pragma unroll
                for (int h = 0; h < 2; ++h) {
                    const long rr = r0 + h * 8;
                    union { __half b[2]; uint32_t u; } H, L;
                    H.b[0] = __float2half_rn(vs[h][0]);
                    H.b[1] = __float2half_rn(vs[h][1]);
                    L.b[0] = __float2half_rn(vs[h][0] - __half2float(H.b[0]));
                    L.b[1] = __float2half_rn(vs[h][1] - __half2float(H.b[1]));
                    *(uint32_t*)(ob + rr * ldo + cc)     = H.u;
                    *(uint32_t*)(ob + rr * ldo + N + cc) = L.u;
                }
            } else {  // MODE 4: fp16 hi only
                __half* ob = (__half*)outv;
                #pragma unroll
                for (int h = 0; h < 2; ++h) {
                    const long rr = r0 + h * 8;
                    union { __half b[2]; uint32_t u; } H;
                    H.b[0] = __float2half_rn(vs[h][0]);
                    H.b[1] = __float2half_rn(vs[h][1]);
                    *(uint32_t*)(ob + rr * N + cc) = H.u;
                }
            }
        }
    }
}

// ---------------- fp32 -> fp16 [hi|lo] converter (A operands) --------------
__global__ __launch_bounds__(256) void convA_kernel(
    const float* __restrict__ in, __half* __restrict__ out, int C, long total4)
{
    const long t = blockIdx.x * 256L + threadIdx.x;
    if (t >= total4) return;
    const long i = t * 4;
    const long r = i / C;
    const int  c = (int)(i - r * C);
    float4 v = *(const float4*)(in + i);
    float vv[4] = {v.x, v.y, v.z, v.w};
    union { __half b[4]; uint2 u; } H, L;
    #pragma unroll
    for (int j = 0; j < 4; ++j) {
        H.b[j] = __float2half_rn(vv[j]);
        L.b[j] = __float2half_rn(vv[j] - __half2float(H.b[j]));
    }
    const long base = r * (2L * C) + c;
    *(uint2*)(out + base)     = H.u;
    *(uint2*)(out + base + C) = L.u;
}

// ---------------- fp32 -> fp16 cast (B operands / weights) -----------------
__global__ __launch_bounds__(256) void convB_kernel(
    const float* __restrict__ in, __half* __restrict__ out, long total4)
{
    const long t = blockIdx.x * 256L + threadIdx.x;
    if (t >= total4) return;
    const long i = t * 4;
    float4 v = *(const float4*)(in + i);
    union { __half b[4]; uint2 u; } H;
    H.b[0] = __float2half_rn(v.x);
    H.b[1] = __float2half_rn(v.y);
    H.b[2] = __float2half_rn(v.z);
    H.b[3] = __float2half_rn(v.w);
    *(uint2*)(out + i) = H.u;
}

// V fp16 [NB,S,A] -> Vt fp16 [NB,A,S] transpose
__global__ void __launch_bounds__(1024) convT_kernel(
    const __half* __restrict__ V, __half* __restrict__ Vt)
{
    __shared__ __half t[32][33];
    const int b  = blockIdx.z;
    const int s0 = blockIdx.y * 32, a0 = blockIdx.x * 32;
    const int x = threadIdx.x, y = threadIdx.y;
    t[y][x] = V[((long)b * SS + s0 + y) * AA + a0 + x];
    __syncthreads();
    Vt[((long)b * AA + a0 + y) * (long)SS + (s0 + x)] = t[x][y];
}

// ---------------- fused softmax -> fp16 hi ---------------------------------
__global__ __launch_bounds__(256) void softmax_split_kernel(
    const float* __restrict__ P, __half* __restrict__ PH)
{
    const float* p = P + (long)blockIdx.x * SS;
    __half* o = PH + (long)blockIdx.x * (long)SS;
    const int tid = threadIdx.x, lane = tid & 31, wrp = tid >> 5;
    __shared__ float red[8];

    float v[16];
    #pragma unroll
    for (int j = 0; j < 4; ++j) {
        float4 t = *(const float4*)(p + j * 1024 + tid * 4);
        v[j * 4 + 0] = t.x; v[j * 4 + 1] = t.y; v[j * 4 + 2] = t.z; v[j * 4 + 3] = t.w;
    }

    float mx = v[0];
    #pragma unroll
    for (int i = 1; i < 16; ++i) mx = fmaxf(mx, v[i]);
    #pragma unroll
    for (int off = 16; off; off >>= 1) mx = fmaxf(mx, __shfl_xor_sync(~0u, mx, off));
    if (lane == 0) red[wrp] = mx;
    __syncthreads();
    mx = red[0];
    #pragma unroll
    for (int w = 1; w < 8; ++w) mx = fmaxf(mx, red[w]);
    __syncthreads();

    float sum = 0.0f;
    #pragma unroll
    for (int i = 0; i < 16; ++i) { v[i] = __expf(v[i] - mx); sum += v[i]; }
    #pragma unroll
    for (int off = 16; off; off >>= 1) sum += __shfl_xor_sync(~0u, sum, off);
    if (lane == 0) red[wrp] = sum;
    __syncthreads();
    sum = 0.0f;
    #pragma unroll
    for (int w = 0; w < 8; ++w) sum += red[w];
    const float inv = 1.0f / sum;

    #pragma unroll
    for (int j = 0; j < 4; ++j) {
        const int col = j * 1024 + tid * 4;
        union { __half b[4]; uint2 u; } H;
        #pragma unroll
        for (int q = 0; q < 4; ++q)
            H.b[q] = __float2half_rn(v[j * 4 + q] * inv);
        *(uint2*)(o + col) = H.u;
    }
}

// ---------------- host ----------------
extern "C" void kernel_launch(void* const* d_in, const int* in_sizes, int n_in,
                              void* d_out, int out_size)
{
    const float* x  = (const float*)d_in[0];
    const float* Wq = (const float*)d_in[1];
    const float* bq = (const float*)d_in[2];
    const float* Wk = (const float*)d_in[3];
    const float* bk = (const float*)d_in[4];
    const float* Wv = (const float*)d_in[5];
    const float* bv = (const float*)d_in[6];
    const float* Wo = (const float*)d_in[7];
    const float* bo = (const float*)d_in[8];
    float* out = (float*)d_out;

    float* P;
    __half *xA, *QA, *KB, *Vh, *VT, *PH, *CA, *WqH, *WkH, *WvH, *WoH;
    cudaGetSymbolAddress((void**)&P,  g_P);
    cudaGetSymbolAddress((void**)&xA, g_xA);
    cudaGetSymbolAddress((void**)&QA, g_QA);
    cudaGetSymbolAddress((void**)&KB, g_KB);
    cudaGetSymbolAddress((void**)&Vh, g_Vh);
    cudaGetSymbolAddress((void**)&VT, g_VT);
    cudaGetSymbolAddress((void**)&PH, g_PH);
    cudaGetSymbolAddress((void**)&CA, g_CA);
    cudaGetSymbolAddress((void**)&WqH, g_WqH);
    cudaGetSymbolAddress((void**)&WkH, g_WkH);
    cudaGetSymbolAddress((void**)&WvH, g_WvH);
    cudaGetSymbolAddress((void**)&WoH, g_WoH);

    cudaFuncSetAttribute((const void*)mma_gemm_kernel<0, 2>,
                         cudaFuncAttributeMaxDynamicSharedMemorySize, GEMM_SMEM);
    cudaFuncSetAttribute((const void*)mma_gemm_kernel<3, 2>,
                         cudaFuncAttributeMaxDynamicSharedMemorySize, GEMM_SMEM);
    cudaFuncSetAttribute((const void*)mma_gemm_kernel<4, 2>,
                         cudaFuncAttributeMaxDynamicSharedMemorySize, GEMM_SMEM);
    cudaFuncSetAttribute((const void*)mma_gemm_kernel<3, 1>,
                         cudaFuncAttributeMaxDynamicSharedMemorySize, GEMM_SMEM);

    const float scale = 0.03125f;  // 1/sqrt(1024)

    // convert inputs: x -> fp16 [hi|lo]; weights -> fp16 cast
    long t4 = (long)NTOK * DD / 4;
    convA_kernel<<<(unsigned)((t4 + 255) / 256), 256>>>(x, xA, DD, t4);
    long w4 = (long)AA * DD / 4;
    convB_kernel<<<(unsigned)((w4 + 255) / 256), 256>>>(Wq, WqH, w4);
    convB_kernel<<<(unsigned)((w4 + 255) / 256), 256>>>(Wk, WkH, w4);
    convB_kernel<<<(unsigned)((w4 + 255) / 256), 256>>>(Wv, WvH, w4);
    convB_kernel<<<(unsigned)((w4 + 255) / 256), 256>>>(Wo, WoH, w4);

    // projections (fp16 split-2): Q -> [hi|lo], K -> hi, V -> hi
    dim3 gproj(AA / 128, NTOK / 128, 1);
    mma_gemm_kernel<3, 2><<<gproj, 256, GEMM_SMEM>>>(xA, WqH, bq, QA, AA, DD, 1.0f, NTOK, AA);
    mma_gemm_kernel<4, 2><<<gproj, 256, GEMM_SMEM>>>(xA, WkH, bk, KB, AA, DD, 1.0f, NTOK, AA);
    mma_gemm_kernel<4, 2><<<gproj, 256, GEMM_SMEM>>>(xA, WvH, bv, Vh, AA, DD, 1.0f, NTOK, AA);

    convT_kernel<<<dim3(AA / 32, SS / 32, NB), dim3(32, 32)>>>(Vh, VT);

    // scores (split-2): q_exact . fp16(k) * scale -> fp32 P
    dim3 gsc(SS / 128, SS / 128, NB);
    mma_gemm_kernel<0, 2><<<gsc, 256, GEMM_SMEM>>>(QA, KB, nullptr, P, SS, AA, scale, SS, SS);

    // fused softmax -> fp16 hi
    softmax_split_kernel<<<NB * SS, 256>>>(P, PH);

    // ctx (split-1): fp16(p) . fp16(v) -> fp16 [hi|lo] CA
    dim3 gctx(AA / 128, SS / 128, NB);
    mma_gemm_kernel<3, 1><<<gctx, 256, GEMM_SMEM>>>(PH, VT, nullptr, CA, AA, SS, 1.0f, SS, AA);

    // output projection (split-2): ctx_exact . fp16(Wo) + bo -> fp32 out
    mma_gemm_kernel<0, 2><<<gproj, 256, GEMM_SMEM>>>(CA, WoH, bo, out, DD, AA, 1.0f, NTOK, DD);
}

// round 15
// speedup vs baseline: 2.6451x; 1.2912x over previous
#include <cuda_runtime.h>
#include <cuda_fp16.h>
#include <stdint.h>

#define NB   4
#define SS   4096
#define DD   1024
#define AA   1024
#define NTOK (NB * SS)

// Scratch (device globals: allocation-free rule)
__device__ float  g_P [(size_t)NB * SS * SS];          // fp32 scores
__device__ __half g_xA[(size_t)NTOK * 2 * DD];         // x  fp16 [hi|lo]
__device__ __half g_QH[(size_t)NTOK * AA];             // Q  fp16 hi
__device__ __half g_KB[(size_t)NTOK * AA];             // K  fp16 hi
__device__ __half g_Vh[(size_t)NTOK * AA];             // V  fp16 hi
__device__ __half g_VT[(size_t)NB * AA * SS];          // V^T fp16 hi
__device__ __half g_PH[(size_t)NTOK * SS];             // attn fp16 hi
__device__ __half g_CH[(size_t)NTOK * AA];             // ctx fp16 hi
__device__ __half g_WqH[(size_t)AA * DD];
__device__ __half g_WkH[(size_t)AA * DD];
__device__ __half g_WvH[(size_t)AA * DD];
__device__ __half g_WoH[(size_t)DD * AA];

// ---------------- PTX helpers (sm_103 baseline: no tcgen05/TMA) ----------
__device__ __forceinline__ uint32_t smem_u32(const void* p) {
    uint32_t a;
    asm("{ .reg .u64 t; cvta.to.shared.u64 t, %1; cvt.u32.u64 %0, t; }" : "=r"(a) : "l"(p));
    return a;
}
__device__ __forceinline__ void cp16(uint32_t dst, const void* src) {
    asm volatile("cp.async.cg.shared.global [%0], [%1], 16;" :: "r"(dst), "l"(src));
}
#define CP_COMMIT() asm volatile("cp.async.commit_group;" ::: "memory")
#define CP_WAIT2()  asm volatile("cp.async.wait_group 2;" ::: "memory")

#define LDSM4(R0, R1, R2, R3, ADDR) \
    asm volatile("ldmatrix.sync.aligned.m8n8.x4.shared.b16 {%0,%1,%2,%3}, [%4];" \
                 : "=r"(R0), "=r"(R1), "=r"(R2), "=r"(R3) : "r"(ADDR))

__device__ __forceinline__ void mma_f16(float* d, const uint32_t* a, const uint32_t* b) {
    asm volatile(
        "mma.sync.aligned.m16n8k16.row.col.f32.f16.f16.f32 "
        "{%0,%1,%2,%3}, {%4,%5,%6,%7}, {%8,%9}, {%0,%1,%2,%3};"
        : "+f"(d[0]), "+f"(d[1]), "+f"(d[2]), "+f"(d[3])
        : "r"(a[0]), "r"(a[1]), "r"(a[2]), "r"(a[3]), "r"(b[0]), "r"(b[1]));
}

// ---------------------------------------------------------------------------
// GEMM (fp16 in, fp32 accum): out[M,N] = alpha*A'[M,SPLIT*K]*B'[N,SPLIT*K]^T + bias
// SPLIT=2: A physical [hi|lo] (ldA=2K); B logical [hi|hi] on physical [hi]
//          (ldB=K, bO = gO<K ? gO : gO-K).   out = A_exact * fp16(B).
// SPLIT=1: single pass, ldA=ldB=K.            out = fp16(A) * fp16(B).
// BM=BN=128, BK=32, 8 warps (2x4, warp 64x32), 4-stage cp.async, 2 CTA/SM.
// MODE 0: fp32 [M,N]+bias | 4: fp16 hi [M,N]+bias
// ---------------------------------------------------------------------------
#define BK 32
#define NSTAGE 4
#define STG_BYTES 16384
#define GEMM_SMEM (NSTAGE * STG_BYTES)

template <int MODE, int SPLIT>
__global__ void __launch_bounds__(256, 2) mma_gemm_kernel(
    const __half* __restrict__ A, const __half* __restrict__ B,
    const float* __restrict__ bias, void* __restrict__ outv,
    int N, int Ksec, float alpha, int rowsA, int rowsB)
{
    extern __shared__ __align__(128) char smem[];
    const uint32_t sb = smem_u32(smem);
    const int tid  = threadIdx.x;
    const int lane = tid & 31;
    const int wid  = tid >> 5;
    const int wm   = wid >> 2;       // 0..1
    const int wn   = wid & 3;        // 0..3

    const long ldA = (long)SPLIT * Ksec;
    const long ldB = (long)Ksec;
    const int aRow = blockIdx.z * rowsA + blockIdx.y * 128;
    const int bRow = blockIdx.z * rowsB + blockIdx.x * 128;

    // cp.async loader: 2 A-chunks + 2 B-chunks of 16B per thread
    const int lr0 = tid >> 2;            // 0..63
    const int lr1 = lr0 + 64;
    const int lc  = tid & 3;
    const int sw0 = (lr0 >> 1) & 3;
    const uint32_t dA0 = (uint32_t)(lr0 * 64 + ((lc ^ sw0) * 16));
    const uint32_t dA1 = (uint32_t)(lr1 * 64 + ((lc ^ sw0) * 16));
    const __half* gA0 = A + (long)(aRow + lr0) * ldA + lc * 8;
    const __half* gA1 = A + (long)(aRow + lr1) * ldA + lc * 8;
    const __half* gB0 = B + (long)(bRow + lr0) * ldB + lc * 8;
    const __half* gB1 = B + (long)(bRow + lr1) * ldB + lc * 8;

    // ldmatrix lane addressing
    const int rA  = wm * 64 + (lane & 15);
    const int khA = lane >> 4;
    const int swA = (rA >> 1) & 3;
    const int rB  = wn * 32 + (lane & 7) + ((lane >> 4) << 3);
    const int khB = (lane >> 3) & 1;
    const int swB = (rB >> 1) & 3;

    float acc[4][4][4];
    #pragma unroll
    for (int i = 0; i < 4; ++i)
        #pragma unroll
        for (int j = 0; j < 4; ++j)
            #pragma unroll
            for (int e = 0; e < 4; ++e) acc[i][j][e] = 0.0f;

    const int NT = (SPLIT * Ksec) / BK;
    const long K1 = Ksec;

    // prologue: stages 0..2 (gO < Ksec always since Ksec >= 1024)
    #pragma unroll
    for (int s = 0; s < NSTAGE - 1; ++s) {
        const uint32_t ab = sb + s * STG_BYTES;
        const long go = (long)s * BK;
        cp16(ab + dA0,        gA0 + go);
        cp16(ab + dA1,        gA1 + go);
        cp16(ab + 8192 + dA0, gB0 + go);
        cp16(ab + 8192 + dA1, gB1 + go);
        CP_COMMIT();
    }

    for (int kt = 0; kt < NT; ++kt) {
        CP_WAIT2();
        __syncthreads();

        if (kt + NSTAGE - 1 < NT) {
            const int s = (kt + NSTAGE - 1) % NSTAGE;
            const uint32_t ab = sb + s * STG_BYTES;
            const long gO = (long)(kt + NSTAGE - 1) * BK;
            const long bO = (SPLIT == 2) ? ((gO < K1) ? gO : gO - K1) : gO;
            cp16(ab + dA0,        gA0 + gO);
            cp16(ab + dA1,        gA1 + gO);
            cp16(ab + 8192 + dA0, gB0 + bO);
            cp16(ab + 8192 + dA1, gB1 + bO);
        }
        CP_COMMIT();

        const uint32_t ab = sb + (kt % NSTAGE) * STG_BYTES;
        const uint32_t bb = ab + 8192;

        #pragma unroll
        for (int ks = 0; ks < 2; ++ks) {
            uint32_t a[4][4], b[4][2];
            #pragma unroll
            for (int mf = 0; mf < 4; ++mf) {
                const uint32_t ad = ab + (uint32_t)((rA + mf * 16) * 64 +
                                     (((ks * 2 + khA) ^ swA) * 16));
                LDSM4(a[mf][0], a[mf][1], a[mf][2], a[mf][3], ad);
            }
            #pragma unroll
            for (int nfp = 0; nfp < 2; ++nfp) {
                const uint32_t bd = bb + (uint32_t)((rB + nfp * 16) * 64 +
                                     (((ks * 2 + khB) ^ swB) * 16));
                LDSM4(b[nfp * 2][0], b[nfp * 2][1], b[nfp * 2 + 1][0], b[nfp * 2 + 1][1], bd);
            }
            #pragma unroll
            for (int mf = 0; mf < 4; ++mf)
                #pragma unroll
                for (int nf = 0; nf < 4; ++nf)
                    mma_f16(acc[mf][nf], a[mf], b[nf]);
        }
    }

    // Epilogue
    const long rBase   = (long)(blockIdx.z * rowsA + blockIdx.y * 128) + wm * 64;
    const int  colBase = blockIdx.x * 128 + wn * 32;

    #pragma unroll
    for (int mf = 0; mf < 4; ++mf) {
        const long r0 = rBase + mf * 16 + (lane >> 2);
        #pragma unroll
        for (int nf = 0; nf < 4; ++nf) {
            const int cc = colBase + nf * 8 + (lane & 3) * 2;
            float2 bv = make_float2(0.0f, 0.0f);
            if (bias) bv = *(const float2*)(bias + cc);
            float vs[2][2] = {
                {acc[mf][nf][0] * alpha + bv.x, acc[mf][nf][1] * alpha + bv.y},
                {acc[mf][nf][2] * alpha + bv.x, acc[mf][nf][3] * alpha + bv.y}};

            if (MODE == 0) {
                float* out = (float*)outv;
                *(float2*)(out + r0 * N + cc)       = make_float2(vs[0][0], vs[0][1]);
                *(float2*)(out + (r0 + 8) * N + cc) = make_float2(vs[1][0], vs[1][1]);
            } else {  // MODE 4: fp16 hi only
                __half* ob = (__half*)outv;
                #pragma unroll
                for (int h = 0; h < 2; ++h) {
                    const long rr = r0 + h * 8;
                    union { __half b[2]; uint32_t u; } H;
                    H.b[0] = __float2half_rn(vs[h][0]);
                    H.b[1] = __float2half_rn(vs[h][1]);
                    *(uint32_t*)(ob + rr * N + cc) = H.u;
                }
            }
        }
    }
}

// ---------------- fp32 -> fp16 [hi|lo] converter (x) -----------------------
__global__ __launch_bounds__(256) void convA_kernel(
    const float* __restrict__ in, __half* __restrict__ out, int C, long total4)
{
    const long t = blockIdx.x * 256L + threadIdx.x;
    if (t >= total4) return;
    const long i = t * 4;
    const long r = i / C;
    const int  c = (int)(i - r * C);
    float4 v = *(const float4*)(in + i);
    float vv[4] = {v.x, v.y, v.z, v.w};
    union { __half b[4]; uint2 u; } H, L;
    #pragma unroll
    for (int j = 0; j < 4; ++j) {
        H.b[j] = __float2half_rn(vv[j]);
        L.b[j] = __float2half_rn(vv[j] - __half2float(H.b[j]));
    }
    const long base = r * (2L * C) + c;
    *(uint2*)(out + base)     = H.u;
    *(uint2*)(out + base + C) = L.u;
}

// ---------------- fp32 -> fp16 cast (weights) ------------------------------
__global__ __launch_bounds__(256) void convB_kernel(
    const float* __restrict__ in, __half* __restrict__ out, long total4)
{
    const long t = blockIdx.x * 256L + threadIdx.x;
    if (t >= total4) return;
    const long i = t * 4;
    float4 v = *(const float4*)(in + i);
    union { __half b[4]; uint2 u; } H;
    H.b[0] = __float2half_rn(v.x);
    H.b[1] = __float2half_rn(v.y);
    H.b[2] = __float2half_rn(v.z);
    H.b[3] = __float2half_rn(v.w);
    *(uint2*)(out + i) = H.u;
}

// V fp16 [NB,S,A] -> Vt fp16 [NB,A,S] transpose
__global__ void __launch_bounds__(1024) convT_kernel(
    const __half* __restrict__ V, __half* __restrict__ Vt)
{
    __shared__ __half t[32][33];
    const int b  = blockIdx.z;
    const int s0 = blockIdx.y * 32, a0 = blockIdx.x * 32;
    const int x = threadIdx.x, y = threadIdx.y;
    t[y][x] = V[((long)b * SS + s0 + y) * AA + a0 + x];
    __syncthreads();
    Vt[((long)b * AA + a0 + y) * (long)SS + (s0 + x)] = t[x][y];
}

// ---------------- fused softmax -> fp16 hi ---------------------------------
__global__ __launch_bounds__(256) void softmax_split_kernel(
    const float* __restrict__ P, __half* __restrict__ PH)
{
    const float* p = P + (long)blockIdx.x * SS;
    __half* o = PH + (long)blockIdx.x * (long)SS;
    const int tid = threadIdx.x, lane = tid & 31, wrp = tid >> 5;
    __shared__ float red[8];

    float v[16];
    #pragma unroll
    for (int j = 0; j < 4; ++j) {
        float4 t = *(const float4*)(p + j * 1024 + tid * 4);
        v[j * 4 + 0] = t.x; v[j * 4 + 1] = t.y; v[j * 4 + 2] = t.z; v[j * 4 + 3] = t.w;
    }

    float mx = v[0];
    #pragma unroll
    for (int i = 1; i < 16; ++i) mx = fmaxf(mx, v[i]);
    #pragma unroll
    for (int off = 16; off; off >>= 1) mx = fmaxf(mx, __shfl_xor_sync(~0u, mx, off));
    if (lane == 0) red[wrp] = mx;
    __syncthreads();
    mx = red[0];
    #pragma unroll
    for (int w = 1; w < 8; ++w) mx = fmaxf(mx, red[w]);
    __syncthreads();

    float sum = 0.0f;
    #pragma unroll
    for (int i = 0; i < 16; ++i) { v[i] = __expf(v[i] - mx); sum += v[i]; }
    #pragma unroll
    for (int off = 16; off; off >>= 1) sum += __shfl_xor_sync(~0u, sum, off);
    if (lane == 0) red[wrp] = sum;
    __syncthreads();
    sum = 0.0f;
    #pragma unroll
    for (int w = 0; w < 8; ++w) sum += red[w];
    const float inv = 1.0f / sum;

    #pragma unroll
    for (int j = 0; j < 4; ++j) {
        const int col = j * 1024 + tid * 4;
        union { __half b[4]; uint2 u; } H;
        #pragma unroll
        for (int q = 0; q < 4; ++q)
            H.b[q] = __float2half_rn(v[j * 4 + q] * inv);
        *(uint2*)(o + col) = H.u;
    }
}

// ---------------- host ----------------
extern "C" void kernel_launch(void* const* d_in, const int* in_sizes, int n_in,
                              void* d_out, int out_size)
{
    const float* x  = (const float*)d_in[0];
    const float* Wq = (const float*)d_in[1];
    const float* bq = (const float*)d_in[2];
    const float* Wk = (const float*)d_in[3];
    const float* bk = (const float*)d_in[4];
    const float* Wv = (const float*)d_in[5];
    const float* bv = (const float*)d_in[6];
    const float* Wo = (const float*)d_in[7];
    const float* bo = (const float*)d_in[8];
    float* out = (float*)d_out;

    float* P;
    __half *xA, *QH, *KB, *Vh, *VT, *PH, *CH, *WqH, *WkH, *WvH, *WoH;
    cudaGetSymbolAddress((void**)&P,  g_P);
    cudaGetSymbolAddress((void**)&xA, g_xA);
    cudaGetSymbolAddress((void**)&QH, g_QH);
    cudaGetSymbolAddress((void**)&KB, g_KB);
    cudaGetSymbolAddress((void**)&Vh, g_Vh);
    cudaGetSymbolAddress((void**)&VT, g_VT);
    cudaGetSymbolAddress((void**)&PH, g_PH);
    cudaGetSymbolAddress((void**)&CH, g_CH);
    cudaGetSymbolAddress((void**)&WqH, g_WqH);
    cudaGetSymbolAddress((void**)&WkH, g_WkH);
    cudaGetSymbolAddress((void**)&WvH, g_WvH);
    cudaGetSymbolAddress((void**)&WoH, g_WoH);

    cudaFuncSetAttribute((const void*)mma_gemm_kernel<0, 2>,
                         cudaFuncAttributeMaxDynamicSharedMemorySize, GEMM_SMEM);
    cudaFuncSetAttribute((const void*)mma_gemm_kernel<4, 2>,
                         cudaFuncAttributeMaxDynamicSharedMemorySize, GEMM_SMEM);
    cudaFuncSetAttribute((const void*)mma_gemm_kernel<0, 1>,
                         cudaFuncAttributeMaxDynamicSharedMemorySize, GEMM_SMEM);
    cudaFuncSetAttribute((const void*)mma_gemm_kernel<4, 1>,
                         cudaFuncAttributeMaxDynamicSharedMemorySize, GEMM_SMEM);

    const float scale = 0.03125f;  // 1/sqrt(1024)

    // convert inputs: x -> fp16 [hi|lo]; weights -> fp16 cast
    long t4 = (long)NTOK * DD / 4;
    convA_kernel<<<(unsigned)((t4 + 255) / 256), 256>>>(x, xA, DD, t4);
    long w4 = (long)AA * DD / 4;
    convB_kernel<<<(unsigned)((w4 + 255) / 256), 256>>>(Wq, WqH, w4);
    convB_kernel<<<(unsigned)((w4 + 255) / 256), 256>>>(Wk, WkH, w4);
    convB_kernel<<<(unsigned)((w4 + 255) / 256), 256>>>(Wv, WvH, w4);
    convB_kernel<<<(unsigned)((w4 + 255) / 256), 256>>>(Wo, WoH, w4);

    // projections (split-2, x_exact . fp16(W)): Q/K/V -> fp16 hi
    dim3 gproj(AA / 128, NTOK / 128, 1);
    mma_gemm_kernel<4, 2><<<gproj, 256, GEMM_SMEM>>>(xA, WqH, bq, QH, AA, DD, 1.0f, NTOK, AA);
    mma_gemm_kernel<4, 2><<<gproj, 256, GEMM_SMEM>>>(xA, WkH, bk, KB, AA, DD, 1.0f, NTOK, AA);
    mma_gemm_kernel<4, 2><<<gproj, 256, GEMM_SMEM>>>(xA, WvH, bv, Vh, AA, DD, 1.0f, NTOK, AA);

    convT_kernel<<<dim3(AA / 32, SS / 32, NB), dim3(32, 32)>>>(Vh, VT);

    // scores (split-1): fp16(q) . fp16(k) * scale -> fp32 P
    dim3 gsc(SS / 128, SS / 128, NB);
    mma_gemm_kernel<0, 1><<<gsc, 256, GEMM_SMEM>>>(QH, KB, nullptr, P, SS, AA, scale, SS, SS);

    // fused softmax -> fp16 hi
    softmax_split_kernel<<<NB * SS, 256>>>(P, PH);

    // ctx (split-1): fp16(p) . fp16(v) -> fp16 hi CH
    dim3 gctx(AA / 128, SS / 128, NB);
    mma_gemm_kernel<4, 1><<<gctx, 256, GEMM_SMEM>>>(PH, VT, nullptr, CH, AA, SS, 1.0f, SS, AA);

    // output projection (split-1): fp16(ctx) . fp16(Wo) + bo -> fp32 out
    mma_gemm_kernel<0, 1><<<gproj, 256, GEMM_SMEM>>>(CH, WoH, bo, out, DD, AA, 1.0f, NTOK, DD);
}

// round 16
// speedup vs baseline: 3.1649x; 1.1965x over previous
#include <cuda_runtime.h>
#include <cuda_fp16.h>
#include <stdint.h>

#define NB   4
#define SS   4096
#define DD   1024
#define AA   1024
#define NTOK (NB * SS)

// Scratch (device globals: allocation-free rule)
__device__ float  g_P   [(size_t)NB * SS * SS];        // fp32 scores
__device__ __half g_xH  [(size_t)NTOK * DD];           // x   fp16
__device__ __half g_QKV [(size_t)NTOK * 3 * AA];       // Q|K|V fp16, row stride 3072
__device__ __half g_VT  [(size_t)NB * AA * SS];        // V^T fp16
__device__ __half g_PH  [(size_t)NTOK * SS];           // attn fp16
__device__ __half g_CH  [(size_t)NTOK * AA];           // ctx fp16
__device__ __half g_WH  [(size_t)3 * AA * DD];         // Wq|Wk|Wv fp16
__device__ __half g_WoH [(size_t)DD * AA];             // Wo fp16
__device__ float  g_bqkv[3 * AA];                      // bq|bk|bv

// ---------------- PTX helpers (sm_103 baseline: no tcgen05/TMA) ----------
__device__ __forceinline__ uint32_t smem_u32(const void* p) {
    uint32_t a;
    asm("{ .reg .u64 t; cvta.to.shared.u64 t, %1; cvt.u32.u64 %0, t; }" : "=r"(a) : "l"(p));
    return a;
}
__device__ __forceinline__ void cp16(uint32_t dst, const void* src) {
    asm volatile("cp.async.cg.shared.global [%0], [%1], 16;" :: "r"(dst), "l"(src));
}
#define CP_COMMIT() asm volatile("cp.async.commit_group;" ::: "memory")
#define CP_WAIT2()  asm volatile("cp.async.wait_group 2;" ::: "memory")

#define LDSM4(R0, R1, R2, R3, ADDR) \
    asm volatile("ldmatrix.sync.aligned.m8n8.x4.shared.b16 {%0,%1,%2,%3}, [%4];" \
                 : "=r"(R0), "=r"(R1), "=r"(R2), "=r"(R3) : "r"(ADDR))

__device__ __forceinline__ void mma_f16(float* d, const uint32_t* a, const uint32_t* b) {
    asm volatile(
        "mma.sync.aligned.m16n8k16.row.col.f32.f16.f16.f32 "
        "{%0,%1,%2,%3}, {%4,%5,%6,%7}, {%8,%9}, {%0,%1,%2,%3};"
        : "+f"(d[0]), "+f"(d[1]), "+f"(d[2]), "+f"(d[3])
        : "r"(a[0]), "r"(a[1]), "r"(a[2]), "r"(a[3]), "r"(b[0]), "r"(b[1]));
}

// ---------------------------------------------------------------------------
// GEMM (fp16 in, fp32 accum): out[M,N] = alpha * A[M,K] * B[N,K]^T + bias
// Explicit row strides ldA/ldB (elements) so operands may live inside wider
// matrices (e.g. K inside the fused QKV buffer).
// BM=BN=128, BK=32, 8 warps (2x4, warp 64x32), 4-stage cp.async, 2 CTA/SM.
// MODE 0: fp32 out + bias | 4: fp16 out + bias
// ---------------------------------------------------------------------------
#define BK 32
#define NSTAGE 4
#define STG_BYTES 16384
#define GEMM_SMEM (NSTAGE * STG_BYTES)

template <int MODE>
__global__ void __launch_bounds__(256, 2) mma_gemm_kernel(
    const __half* __restrict__ A, const __half* __restrict__ B,
    const float* __restrict__ bias, void* __restrict__ outv,
    int N, int K, long ldA, long ldB, float alpha, int rowsA, int rowsB)
{
    extern __shared__ __align__(128) char smem[];
    const uint32_t sb = smem_u32(smem);
    const int tid  = threadIdx.x;
    const int lane = tid & 31;
    const int wid  = tid >> 5;
    const int wm   = wid >> 2;       // 0..1
    const int wn   = wid & 3;        // 0..3

    const int aRow = blockIdx.z * rowsA + blockIdx.y * 128;
    const int bRow = blockIdx.z * rowsB + blockIdx.x * 128;

    // cp.async loader: 2 A-chunks + 2 B-chunks of 16B per thread
    const int lr0 = tid >> 2;            // 0..63
    const int lr1 = lr0 + 64;
    const int lc  = tid & 3;
    const int sw0 = (lr0 >> 1) & 3;
    const uint32_t dA0 = (uint32_t)(lr0 * 64 + ((lc ^ sw0) * 16));
    const uint32_t dA1 = (uint32_t)(lr1 * 64 + ((lc ^ sw0) * 16));
    const __half* gA0 = A + (long)(aRow + lr0) * ldA + lc * 8;
    const __half* gA1 = A + (long)(aRow + lr1) * ldA + lc * 8;
    const __half* gB0 = B + (long)(bRow + lr0) * ldB + lc * 8;
    const __half* gB1 = B + (long)(bRow + lr1) * ldB + lc * 8;

    // ldmatrix lane addressing
    const int rA  = wm * 64 + (lane & 15);
    const int khA = lane >> 4;
    const int swA = (rA >> 1) & 3;
    const int rB  = wn * 32 + (lane & 7) + ((lane >> 4) << 3);
    const int khB = (lane >> 3) & 1;
    const int swB = (rB >> 1) & 3;

    float acc[4][4][4];
    #pragma unroll
    for (int i = 0; i < 4; ++i)
        #pragma unroll
        for (int j = 0; j < 4; ++j)
            #pragma unroll
            for (int e = 0; e < 4; ++e) acc[i][j][e] = 0.0f;

    const int NT = K / BK;

    // prologue: stages 0..2
    #pragma unroll
    for (int s = 0; s < NSTAGE - 1; ++s) {
        const uint32_t ab = sb + s * STG_BYTES;
        const long go = (long)s * BK;
        cp16(ab + dA0,        gA0 + go);
        cp16(ab + dA1,        gA1 + go);
        cp16(ab + 8192 + dA0, gB0 + go);
        cp16(ab + 8192 + dA1, gB1 + go);
        CP_COMMIT();
    }

    for (int kt = 0; kt < NT; ++kt) {
        CP_WAIT2();
        __syncthreads();

        if (kt + NSTAGE - 1 < NT) {
            const int s = (kt + NSTAGE - 1) % NSTAGE;
            const uint32_t ab = sb + s * STG_BYTES;
            const long gO = (long)(kt + NSTAGE - 1) * BK;
            cp16(ab + dA0,        gA0 + gO);
            cp16(ab + dA1,        gA1 + gO);
            cp16(ab + 8192 + dA0, gB0 + gO);
            cp16(ab + 8192 + dA1, gB1 + gO);
        }
        CP_COMMIT();

        const uint32_t ab = sb + (kt % NSTAGE) * STG_BYTES;
        const uint32_t bb = ab + 8192;

        #pragma unroll
        for (int ks = 0; ks < 2; ++ks) {
            uint32_t a[4][4], b[4][2];
            #pragma unroll
            for (int mf = 0; mf < 4; ++mf) {
                const uint32_t ad = ab + (uint32_t)((rA + mf * 16) * 64 +
                                     (((ks * 2 + khA) ^ swA) * 16));
                LDSM4(a[mf][0], a[mf][1], a[mf][2], a[mf][3], ad);
            }
            #pragma unroll
            for (int nfp = 0; nfp < 2; ++nfp) {
                const uint32_t bd = bb + (uint32_t)((rB + nfp * 16) * 64 +
                                     (((ks * 2 + khB) ^ swB) * 16));
                LDSM4(b[nfp * 2][0], b[nfp * 2][1], b[nfp * 2 + 1][0], b[nfp * 2 + 1][1], bd);
            }
            #pragma unroll
            for (int mf = 0; mf < 4; ++mf)
                #pragma unroll
                for (int nf = 0; nf < 4; ++nf)
                    mma_f16(acc[mf][nf], a[mf], b[nf]);
        }
    }

    // Epilogue
    const long rBase   = (long)(blockIdx.z * rowsA + blockIdx.y * 128) + wm * 64;
    const int  colBase = blockIdx.x * 128 + wn * 32;

    #pragma unroll
    for (int mf = 0; mf < 4; ++mf) {
        const long r0 = rBase + mf * 16 + (lane >> 2);
        #pragma unroll
        for (int nf = 0; nf < 4; ++nf) {
            const int cc = colBase + nf * 8 + (lane & 3) * 2;
            float2 bv = make_float2(0.0f, 0.0f);
            if (bias) bv = *(const float2*)(bias + cc);
            float vs[2][2] = {
                {acc[mf][nf][0] * alpha + bv.x, acc[mf][nf][1] * alpha + bv.y},
                {acc[mf][nf][2] * alpha + bv.x, acc[mf][nf][3] * alpha + bv.y}};

            if (MODE == 0) {
                float* out = (float*)outv;
                *(float2*)(out + r0 * N + cc)       = make_float2(vs[0][0], vs[0][1]);
                *(float2*)(out + (r0 + 8) * N + cc) = make_float2(vs[1][0], vs[1][1]);
            } else {  // MODE 4: fp16
                __half* ob = (__half*)outv;
                #pragma unroll
                for (int h = 0; h < 2; ++h) {
                    const long rr = r0 + h * 8;
                    union { __half b[2]; uint32_t u; } H;
                    H.b[0] = __float2half_rn(vs[h][0]);
                    H.b[1] = __float2half_rn(vs[h][1]);
                    *(uint32_t*)(ob + rr * N + cc) = H.u;
                }
            }
        }
    }
}

// ---------------- fp32 -> fp16 cast -----------------------------------------
__global__ __launch_bounds__(256) void convB_kernel(
    const float* __restrict__ in, __half* __restrict__ out, long total4)
{
    const long t = blockIdx.x * 256L + threadIdx.x;
    if (t >= total4) return;
    const long i = t * 4;
    float4 v = *(const float4*)(in + i);
    union { __half b[4]; uint2 u; } H;
    H.b[0] = __float2half_rn(v.x);
    H.b[1] = __float2half_rn(v.y);
    H.b[2] = __float2half_rn(v.z);
    H.b[3] = __float2half_rn(v.w);
    *(uint2*)(out + i) = H.u;
}

// V (inside QKV, row stride 3*AA, col offset 2*AA) -> Vt [NB,A,S] fp16
__global__ void __launch_bounds__(1024) convT_kernel(
    const __half* __restrict__ QKV, __half* __restrict__ Vt)
{
    __shared__ __half t[32][33];
    const int b  = blockIdx.z;
    const int s0 = blockIdx.y * 32, a0 = blockIdx.x * 32;
    const int x = threadIdx.x, y = threadIdx.y;
    t[y][x] = QKV[((long)b * SS + s0 + y) * (3L * AA) + 2 * AA + a0 + x];
    __syncthreads();
    Vt[((long)b * AA + a0 + y) * (long)SS + (s0 + x)] = t[x][y];
}

// ---------------- fused softmax -> fp16 -------------------------------------
__global__ __launch_bounds__(256) void softmax_split_kernel(
    const float* __restrict__ P, __half* __restrict__ PH)
{
    const float* p = P + (long)blockIdx.x * SS;
    __half* o = PH + (long)blockIdx.x * (long)SS;
    const int tid = threadIdx.x, lane = tid & 31, wrp = tid >> 5;
    __shared__ float red[8];

    float v[16];
    #pragma unroll
    for (int j = 0; j < 4; ++j) {
        float4 t = *(const float4*)(p + j * 1024 + tid * 4);
        v[j * 4 + 0] = t.x; v[j * 4 + 1] = t.y; v[j * 4 + 2] = t.z; v[j * 4 + 3] = t.w;
    }

    float mx = v[0];
    #pragma unroll
    for (int i = 1; i < 16; ++i) mx = fmaxf(mx, v[i]);
    #pragma unroll
    for (int off = 16; off; off >>= 1) mx = fmaxf(mx, __shfl_xor_sync(~0u, mx, off));
    if (lane == 0) red[wrp] = mx;
    __syncthreads();
    mx = red[0];
    #pragma unroll
    for (int w = 1; w < 8; ++w) mx = fmaxf(mx, red[w]);
    __syncthreads();

    float sum = 0.0f;
    #pragma unroll
    for (int i = 0; i < 16; ++i) { v[i] = __expf(v[i] - mx); sum += v[i]; }
    #pragma unroll
    for (int off = 16; off; off >>= 1) sum += __shfl_xor_sync(~0u, sum, off);
    if (lane == 0) red[wrp] = sum;
    __syncthreads();
    sum = 0.0f;
    #pragma unroll
    for (int w = 0; w < 8; ++w) sum += red[w];
    const float inv = 1.0f / sum;

    #pragma unroll
    for (int j = 0; j < 4; ++j) {
        const int col = j * 1024 + tid * 4;
        union { __half b[4]; uint2 u; } H;
        #pragma unroll
        for (int q = 0; q < 4; ++q)
            H.b[q] = __float2half_rn(v[j * 4 + q] * inv);
        *(uint2*)(o + col) = H.u;
    }
}

// ---------------- host ----------------
extern "C" void kernel_launch(void* const* d_in, const int* in_sizes, int n_in,
                              void* d_out, int out_size)
{
    const float* x  = (const float*)d_in[0];
    const float* Wq = (const float*)d_in[1];
    const float* bq = (const float*)d_in[2];
    const float* Wk = (const float*)d_in[3];
    const float* bk = (const float*)d_in[4];
    const float* Wv = (const float*)d_in[5];
    const float* bv = (const float*)d_in[6];
    const float* Wo = (const float*)d_in[7];
    const float* bo = (const float*)d_in[8];
    float* out = (float*)d_out;

    float *P, *bqkv;
    __half *xH, *QKV, *VT, *PH, *CH, *WH, *WoH;
    cudaGetSymbolAddress((void**)&P,   g_P);
    cudaGetSymbolAddress((void**)&xH,  g_xH);
    cudaGetSymbolAddress((void**)&QKV, g_QKV);
    cudaGetSymbolAddress((void**)&VT,  g_VT);
    cudaGetSymbolAddress((void**)&PH,  g_PH);
    cudaGetSymbolAddress((void**)&CH,  g_CH);
    cudaGetSymbolAddress((void**)&WH,  g_WH);
    cudaGetSymbolAddress((void**)&WoH, g_WoH);
    cudaGetSymbolAddress((void**)&bqkv, g_bqkv);

    cudaFuncSetAttribute((const void*)mma_gemm_kernel<0>,
                         cudaFuncAttributeMaxDynamicSharedMemorySize, GEMM_SMEM);
    cudaFuncSetAttribute((const void*)mma_gemm_kernel<4>,
                         cudaFuncAttributeMaxDynamicSharedMemorySize, GEMM_SMEM);

    const float scale = 0.03125f;  // 1/sqrt(1024)

    // convert: x and weights -> fp16; biases -> combined buffer
    long t4 = (long)NTOK * DD / 4;
    convB_kernel<<<(unsigned)((t4 + 255) / 256), 256>>>(x, xH, t4);
    long w4 = (long)AA * DD / 4;
    convB_kernel<<<(unsigned)((w4 + 255) / 256), 256>>>(Wq, WH, w4);
    convB_kernel<<<(unsigned)((w4 + 255) / 256), 256>>>(Wk, WH + (size_t)AA * DD, w4);
    convB_kernel<<<(unsigned)((w4 + 255) / 256), 256>>>(Wv, WH + (size_t)2 * AA * DD, w4);
    convB_kernel<<<(unsigned)((w4 + 255) / 256), 256>>>(Wo, WoH, w4);
    cudaMemcpyAsync(bqkv,          bq, AA * sizeof(float), cudaMemcpyDeviceToDevice);
    cudaMemcpyAsync(bqkv + AA,     bk, AA * sizeof(float), cudaMemcpyDeviceToDevice);
    cudaMemcpyAsync(bqkv + 2 * AA, bv, AA * sizeof(float), cudaMemcpyDeviceToDevice);

    // fused QKV projection: [NTOK,1024] x [3072,1024]^T -> QKV [NTOK,3072]
    dim3 gproj(3 * AA / 128, NTOK / 128, 1);
    mma_gemm_kernel<4><<<gproj, 256, GEMM_SMEM>>>(
        xH, WH, bqkv, QKV, 3 * AA, DD, DD, DD, 1.0f, NTOK, 3 * AA);

    // V^T from QKV
    convT_kernel<<<dim3(AA / 32, SS / 32, NB), dim3(32, 32)>>>(QKV, VT);

    // scores: fp16(q).fp16(k)*scale -> fp32 P   (Q,K inside QKV, stride 3072)
    dim3 gsc(SS / 128, SS / 128, NB);
    mma_gemm_kernel<0><<<gsc, 256, GEMM_SMEM>>>(
        QKV, QKV + AA, nullptr, P, SS, AA, 3 * AA, 3 * AA, scale, SS, SS);

    // fused softmax -> fp16 PH
    softmax_split_kernel<<<NB * SS, 256>>>(P, PH);

    // ctx: fp16(p).fp16(v) -> fp16 CH
    dim3 gctx(AA / 128, SS / 128, NB);
    mma_gemm_kernel<4><<<gctx, 256, GEMM_SMEM>>>(
        PH, VT, nullptr, CH, AA, SS, SS, SS, 1.0f, SS, AA);

    // output projection: fp16(ctx).fp16(Wo) + bo -> fp32 out
    dim3 gout(DD / 128, NTOK / 128, 1);
    mma_gemm_kernel<0><<<gout, 256, GEMM_SMEM>>>(
        CH, WoH, bo, out, DD, AA, AA, AA, 1.0f, NTOK, DD);
}

// round 17
// speedup vs baseline: 3.2382x; 1.0232x over previous
#include <cuda_runtime.h>
#include <cuda_fp16.h>
#include <stdint.h>

#define NB   4
#define SS   4096
#define DD   1024
#define AA   1024
#define NTOK (NB * SS)

// Scratch (device globals: allocation-free rule)
__device__ __half g_P16 [(size_t)NB * SS * SS];        // fp16 scores
__device__ __half g_xH  [(size_t)NTOK * DD];           // x   fp16
__device__ __half g_QKV [(size_t)NTOK * 3 * AA];       // Q|K|V fp16, row stride 3072
__device__ __half g_VT  [(size_t)NB * AA * SS];        // V^T fp16
__device__ __half g_PH  [(size_t)NTOK * SS];           // attn fp16
__device__ __half g_CH  [(size_t)NTOK * AA];           // ctx fp16
__device__ __half g_WH  [(size_t)3 * AA * DD];         // Wq|Wk|Wv fp16
__device__ __half g_WoH [(size_t)DD * AA];             // Wo fp16
__device__ float  g_bqkv[3 * AA];                      // bq|bk|bv

// ---------------- PTX helpers (sm_103 baseline: no tcgen05/TMA) ----------
__device__ __forceinline__ uint32_t smem_u32(const void* p) {
    uint32_t a;
    asm("{ .reg .u64 t; cvta.to.shared.u64 t, %1; cvt.u32.u64 %0, t; }" : "=r"(a) : "l"(p));
    return a;
}
__device__ __forceinline__ void cp16(uint32_t dst, const void* src) {
    asm volatile("cp.async.cg.shared.global [%0], [%1], 16;" :: "r"(dst), "l"(src));
}
#define CP_COMMIT() asm volatile("cp.async.commit_group;" ::: "memory")
#define CP_WAIT2()  asm volatile("cp.async.wait_group 2;" ::: "memory")

#define LDSM4(R0, R1, R2, R3, ADDR) \
    asm volatile("ldmatrix.sync.aligned.m8n8.x4.shared.b16 {%0,%1,%2,%3}, [%4];" \
                 : "=r"(R0), "=r"(R1), "=r"(R2), "=r"(R3) : "r"(ADDR))

__device__ __forceinline__ void mma_f16(float* d, const uint32_t* a, const uint32_t* b) {
    asm volatile(
        "mma.sync.aligned.m16n8k16.row.col.f32.f16.f16.f32 "
        "{%0,%1,%2,%3}, {%4,%5,%6,%7}, {%8,%9}, {%0,%1,%2,%3};"
        : "+f"(d[0]), "+f"(d[1]), "+f"(d[2]), "+f"(d[3])
        : "r"(a[0]), "r"(a[1]), "r"(a[2]), "r"(a[3]), "r"(b[0]), "r"(b[1]));
}

// ---------------------------------------------------------------------------
// GEMM (fp16 in, fp32 accum): out[M,N] = alpha * A[M,K] * B[N,K]^T + bias
// Explicit row strides ldA/ldB so operands may live inside wider matrices.
// BM=BN=128, BK=32, 8 warps (2x4, warp 64x32), 4-stage cp.async, 2 CTA/SM.
// MODE 0: fp32 out + bias | 4: fp16 out (+ optional bias)
// ---------------------------------------------------------------------------
#define BK 32
#define NSTAGE 4
#define STG_BYTES 16384
#define GEMM_SMEM (NSTAGE * STG_BYTES)

template <int MODE>
__global__ void __launch_bounds__(256, 2) mma_gemm_kernel(
    const __half* __restrict__ A, const __half* __restrict__ B,
    const float* __restrict__ bias, void* __restrict__ outv,
    int N, int K, long ldA, long ldB, float alpha, int rowsA, int rowsB)
{
    extern __shared__ __align__(128) char smem[];
    const uint32_t sb = smem_u32(smem);
    const int tid  = threadIdx.x;
    const int lane = tid & 31;
    const int wid  = tid >> 5;
    const int wm   = wid >> 2;       // 0..1
    const int wn   = wid & 3;        // 0..3

    const int aRow = blockIdx.z * rowsA + blockIdx.y * 128;
    const int bRow = blockIdx.z * rowsB + blockIdx.x * 128;

    // cp.async loader: 2 A-chunks + 2 B-chunks of 16B per thread
    const int lr0 = tid >> 2;            // 0..63
    const int lr1 = lr0 + 64;
    const int lc  = tid & 3;
    const int sw0 = (lr0 >> 1) & 3;
    const uint32_t dA0 = (uint32_t)(lr0 * 64 + ((lc ^ sw0) * 16));
    const uint32_t dA1 = (uint32_t)(lr1 * 64 + ((lc ^ sw0) * 16));
    const __half* gA0 = A + (long)(aRow + lr0) * ldA + lc * 8;
    const __half* gA1 = A + (long)(aRow + lr1) * ldA + lc * 8;
    const __half* gB0 = B + (long)(bRow + lr0) * ldB + lc * 8;
    const __half* gB1 = B + (long)(bRow + lr1) * ldB + lc * 8;

    // ldmatrix lane addressing
    const int rA  = wm * 64 + (lane & 15);
    const int khA = lane >> 4;
    const int swA = (rA >> 1) & 3;
    const int rB  = wn * 32 + (lane & 7) + ((lane >> 4) << 3);
    const int khB = (lane >> 3) & 1;
    const int swB = (rB >> 1) & 3;

    float acc[4][4][4];
    #pragma unroll
    for (int i = 0; i < 4; ++i)
        #pragma unroll
        for (int j = 0; j < 4; ++j)
            #pragma unroll
            for (int e = 0; e < 4; ++e) acc[i][j][e] = 0.0f;

    const int NT = K / BK;

    #pragma unroll
    for (int s = 0; s < NSTAGE - 1; ++s) {
        const uint32_t ab = sb + s * STG_BYTES;
        const long go = (long)s * BK;
        cp16(ab + dA0,        gA0 + go);
        cp16(ab + dA1,        gA1 + go);
        cp16(ab + 8192 + dA0, gB0 + go);
        cp16(ab + 8192 + dA1, gB1 + go);
        CP_COMMIT();
    }

    for (int kt = 0; kt < NT; ++kt) {
        CP_WAIT2();
        __syncthreads();

        if (kt + NSTAGE - 1 < NT) {
            const int s = (kt + NSTAGE - 1) % NSTAGE;
            const uint32_t ab = sb + s * STG_BYTES;
            const long gO = (long)(kt + NSTAGE - 1) * BK;
            cp16(ab + dA0,        gA0 + gO);
            cp16(ab + dA1,        gA1 + gO);
            cp16(ab + 8192 + dA0, gB0 + gO);
            cp16(ab + 8192 + dA1, gB1 + gO);
        }
        CP_COMMIT();

        const uint32_t ab = sb + (kt % NSTAGE) * STG_BYTES;
        const uint32_t bb = ab + 8192;

        #pragma unroll
        for (int ks = 0; ks < 2; ++ks) {
            uint32_t a[4][4], b[4][2];
            #pragma unroll
            for (int mf = 0; mf < 4; ++mf) {
                const uint32_t ad = ab + (uint32_t)((rA + mf * 16) * 64 +
                                     (((ks * 2 + khA) ^ swA) * 16));
                LDSM4(a[mf][0], a[mf][1], a[mf][2], a[mf][3], ad);
            }
            #pragma unroll
            for (int nfp = 0; nfp < 2; ++nfp) {
                const uint32_t bd = bb + (uint32_t)((rB + nfp * 16) * 64 +
                                     (((ks * 2 + khB) ^ swB) * 16));
                LDSM4(b[nfp * 2][0], b[nfp * 2][1], b[nfp * 2 + 1][0], b[nfp * 2 + 1][1], bd);
            }
            #pragma unroll
            for (int mf = 0; mf < 4; ++mf)
                #pragma unroll
                for (int nf = 0; nf < 4; ++nf)
                    mma_f16(acc[mf][nf], a[mf], b[nf]);
        }
    }

    // Epilogue
    const long rBase   = (long)(blockIdx.z * rowsA + blockIdx.y * 128) + wm * 64;
    const int  colBase = blockIdx.x * 128 + wn * 32;

    #pragma unroll
    for (int mf = 0; mf < 4; ++mf) {
        const long r0 = rBase + mf * 16 + (lane >> 2);
        #pragma unroll
        for (int nf = 0; nf < 4; ++nf) {
            const int cc = colBase + nf * 8 + (lane & 3) * 2;
            float2 bv = make_float2(0.0f, 0.0f);
            if (bias) bv = *(const float2*)(bias + cc);
            float vs[2][2] = {
                {acc[mf][nf][0] * alpha + bv.x, acc[mf][nf][1] * alpha + bv.y},
                {acc[mf][nf][2] * alpha + bv.x, acc[mf][nf][3] * alpha + bv.y}};

            if (MODE == 0) {
                float* out = (float*)outv;
                *(float2*)(out + r0 * N + cc)       = make_float2(vs[0][0], vs[0][1]);
                *(float2*)(out + (r0 + 8) * N + cc) = make_float2(vs[1][0], vs[1][1]);
            } else {  // MODE 4: fp16
                __half* ob = (__half*)outv;
                #pragma unroll
                for (int h = 0; h < 2; ++h) {
                    const long rr = r0 + h * 8;
                    union { __half b[2]; uint32_t u; } H;
                    H.b[0] = __float2half_rn(vs[h][0]);
                    H.b[1] = __float2half_rn(vs[h][1]);
                    *(uint32_t*)(ob + rr * N + cc) = H.u;
                }
            }
        }
    }
}

// ---------------------------------------------------------------------------
// Merged conversion: x -> xH, Wq|Wk|Wv -> WH, Wo -> WoH, biases -> bqkv.
// One launch; segments indexed by quad id.
// ---------------------------------------------------------------------------
#define XQ ((long)NTOK * DD / 4)      // 4,194,304 quads
#define WQ ((long)AA * DD / 4)        //   262,144 quads
#define CONV_TOTAL (XQ + 4 * WQ)      // 5,242,880 quads

__global__ __launch_bounds__(256) void conv_all_kernel(
    const float* __restrict__ x,
    const float* __restrict__ Wq, const float* __restrict__ Wk,
    const float* __restrict__ Wv, const float* __restrict__ Wo,
    const float* __restrict__ bq, const float* __restrict__ bk,
    const float* __restrict__ bv,
    __half* __restrict__ xH, __half* __restrict__ WH,
    __half* __restrict__ WoH, float* __restrict__ bqkv)
{
    const long t = blockIdx.x * 256L + threadIdx.x;
    if (t < 3 * AA)
        bqkv[t] = (t < AA) ? bq[t] : (t < 2 * AA ? bk[t - AA] : bv[t - 2 * AA]);
    if (t >= CONV_TOTAL) return;

    const float* src;
    __half* dst;
    long idx;
    if (t < XQ)               { src = x;  dst = xH;                        idx = t; }
    else if (t < XQ + WQ)     { src = Wq; dst = WH;                        idx = t - XQ; }
    else if (t < XQ + 2 * WQ) { src = Wk; dst = WH + (size_t)AA * DD;      idx = t - XQ - WQ; }
    else if (t < XQ + 3 * WQ) { src = Wv; dst = WH + (size_t)2 * AA * DD;  idx = t - XQ - 2 * WQ; }
    else                      { src = Wo; dst = WoH;                       idx = t - XQ - 3 * WQ; }

    const long i = idx * 4;
    float4 v = *(const float4*)(src + i);
    union { __half b[4]; uint2 u; } H;
    H.b[0] = __float2half_rn(v.x);
    H.b[1] = __float2half_rn(v.y);
    H.b[2] = __float2half_rn(v.z);
    H.b[3] = __float2half_rn(v.w);
    *(uint2*)(dst + i) = H.u;
}

// V (inside QKV, row stride 3*AA, col offset 2*AA) -> Vt [NB,A,S] fp16
__global__ void __launch_bounds__(1024) convT_kernel(
    const __half* __restrict__ QKV, __half* __restrict__ Vt)
{
    __shared__ __half t[32][33];
    const int b  = blockIdx.z;
    const int s0 = blockIdx.y * 32, a0 = blockIdx.x * 32;
    const int x = threadIdx.x, y = threadIdx.y;
    t[y][x] = QKV[((long)b * SS + s0 + y) * (3L * AA) + 2 * AA + a0 + x];
    __syncthreads();
    Vt[((long)b * AA + a0 + y) * (long)SS + (s0 + x)] = t[x][y];
}

// ---------------- softmax: fp16 logits in, fp16 attn out --------------------
__global__ __launch_bounds__(256) void softmax_kernel(
    const __half* __restrict__ P, __half* __restrict__ PH)
{
    const __half* p = P + (long)blockIdx.x * SS;
    __half* o = PH + (long)blockIdx.x * (long)SS;
    const int tid = threadIdx.x, lane = tid & 31, wrp = tid >> 5;
    __shared__ float red[8];

    float v[16];
    #pragma unroll
    for (int j = 0; j < 2; ++j) {
        uint4 u = *(const uint4*)(p + j * 2048 + tid * 8);
        const uint32_t w[4] = {u.x, u.y, u.z, u.w};
        #pragma unroll
        for (int q = 0; q < 4; ++q) {
            float2 f = __half22float2(*(const __half2*)&w[q]);
            v[j * 8 + q * 2 + 0] = f.x;
            v[j * 8 + q * 2 + 1] = f.y;
        }
    }

    float mx = v[0];
    #pragma unroll
    for (int i = 1; i < 16; ++i) mx = fmaxf(mx, v[i]);
    #pragma unroll
    for (int off = 16; off; off >>= 1) mx = fmaxf(mx, __shfl_xor_sync(~0u, mx, off));
    if (lane == 0) red[wrp] = mx;
    __syncthreads();
    mx = red[0];
    #pragma unroll
    for (int w = 1; w < 8; ++w) mx = fmaxf(mx, red[w]);
    __syncthreads();

    float sum = 0.0f;
    #pragma unroll
    for (int i = 0; i < 16; ++i) { v[i] = __expf(v[i] - mx); sum += v[i]; }
    #pragma unroll
    for (int off = 16; off; off >>= 1) sum += __shfl_xor_sync(~0u, sum, off);
    if (lane == 0) red[wrp] = sum;
    __syncthreads();
    sum = 0.0f;
    #pragma unroll
    for (int w = 0; w < 8; ++w) sum += red[w];
    const float inv = 1.0f / sum;

    #pragma unroll
    for (int j = 0; j < 2; ++j) {
        union { __half b[8]; uint4 u; } H;
        #pragma unroll
        for (int q = 0; q < 8; ++q)
            H.b[q] = __float2half_rn(v[j * 8 + q] * inv);
        *(uint4*)(o + j * 2048 + tid * 8) = H.u;
    }
}

// ---------------- host ----------------
extern "C" void kernel_launch(void* const* d_in, const int* in_sizes, int n_in,
                              void* d_out, int out_size)
{
    const float* x  = (const float*)d_in[0];
    const float* Wq = (const float*)d_in[1];
    const float* bq = (const float*)d_in[2];
    const float* Wk = (const float*)d_in[3];
    const float* bk = (const float*)d_in[4];
    const float* Wv = (const float*)d_in[5];
    const float* bv = (const float*)d_in[6];
    const float* Wo = (const float*)d_in[7];
    const float* bo = (const float*)d_in[8];
    float* out = (float*)d_out;

    float* bqkv;
    __half *P16, *xH, *QKV, *VT, *PH, *CH, *WH, *WoH;
    cudaGetSymbolAddress((void**)&P16, g_P16);
    cudaGetSymbolAddress((void**)&xH,  g_xH);
    cudaGetSymbolAddress((void**)&QKV, g_QKV);
    cudaGetSymbolAddress((void**)&VT,  g_VT);
    cudaGetSymbolAddress((void**)&PH,  g_PH);
    cudaGetSymbolAddress((void**)&CH,  g_CH);
    cudaGetSymbolAddress((void**)&WH,  g_WH);
    cudaGetSymbolAddress((void**)&WoH, g_WoH);
    cudaGetSymbolAddress((void**)&bqkv, g_bqkv);

    cudaFuncSetAttribute((const void*)mma_gemm_kernel<0>,
                         cudaFuncAttributeMaxDynamicSharedMemorySize, GEMM_SMEM);
    cudaFuncSetAttribute((const void*)mma_gemm_kernel<4>,
                         cudaFuncAttributeMaxDynamicSharedMemorySize, GEMM_SMEM);

    const float scale = 0.03125f;  // 1/sqrt(1024)

    // merged conversions + bias packing (one launch)
    conv_all_kernel<<<(unsigned)((CONV_TOTAL + 255) / 256), 256>>>(
        x, Wq, Wk, Wv, Wo, bq, bk, bv, xH, WH, WoH, bqkv);

    // fused QKV projection: [NTOK,1024] x [3072,1024]^T -> QKV [NTOK,3072]
    dim3 gproj(3 * AA / 128, NTOK / 128, 1);
    mma_gemm_kernel<4><<<gproj, 256, GEMM_SMEM>>>(
        xH, WH, bqkv, QKV, 3 * AA, DD, DD, DD, 1.0f, NTOK, 3 * AA);

    // V^T from QKV
    convT_kernel<<<dim3(AA / 32, SS / 32, NB), dim3(32, 32)>>>(QKV, VT);

    // scores: fp16(q).fp16(k)*scale -> fp16 P16
    dim3 gsc(SS / 128, SS / 128, NB);
    mma_gemm_kernel<4><<<gsc, 256, GEMM_SMEM>>>(
        QKV, QKV + AA, nullptr, P16, SS, AA, 3 * AA, 3 * AA, scale, SS, SS);

    // softmax fp16 -> fp16 PH
    softmax_kernel<<<NB * SS, 256>>>(P16, PH);

    // ctx: fp16(p).fp16(v) -> fp16 CH
    dim3 gctx(AA / 128, SS / 128, NB);
    mma_gemm_kernel<4><<<gctx, 256, GEMM_SMEM>>>(
        PH, VT, nullptr, CH, AA, SS, SS, SS, 1.0f, SS, AA);

    // output projection: fp16(ctx).fp16(Wo) + bo -> fp32 out
    dim3 gout(DD / 128, NTOK / 128, 1);
    mma_gemm_kernel<0><<<gout, 256, GEMM_SMEM>>>(
        CH, WoH, bo, out, DD, AA, AA, AA, 1.0f, NTOK, DD);
}